// round 13
// baseline (speedup 1.0000x reference)
#include <cuda_runtime.h>
#include <cuda_bf16.h>
#include <math.h>
#include <stdint.h>

#define LAYERS 6
#define Hc 1024
#define NHc 16
#define Dc 64
#define Fc 4096
#define Bc 4
#define Sc 512
#define Mrows (Bc * Sc)
#define LN_EPS 1e-12f
#define GELU_C 0.7978845608028654f

__device__ float g_h[Mrows * Hc];
__device__ float g_q[Mrows * Hc];
__device__ float g_k[Mrows * Hc];
__device__ float g_v[Mrows * Hc];
__device__ float g_a[Mrows * Hc];
__device__ float g_t[Mrows * Hc];
__device__ float g_x1[Mrows * Hc];
__device__ float g_x2[Mrows * Hc];
__device__ float g_x3[Mrows * Hc];
__device__ float g_inter[Mrows * Fc];

// ---------------------------------------------------------------------------
// Helpers
// ---------------------------------------------------------------------------
__device__ __forceinline__ uint32_t smem_u32(const void* p) {
    uint32_t a;
    asm("{ .reg .u64 t; cvta.to.shared.u64 t, %1; cvt.u32.u64 %0, t; }" : "=r"(a) : "l"(p));
    return a;
}
// bf16 hi/lo split: x = hi + lo, packed bf16x2 (x0 low half, x1 high half)
__device__ __forceinline__ void bfsplit2(float x0, float x1, unsigned& hi, unsigned& lo) {
    unsigned h;
    asm("cvt.rn.bf16x2.f32 %0, %1, %2;" : "=r"(h) : "f"(x1), "f"(x0));
    float h0 = __uint_as_float(h << 16);
    float h1 = __uint_as_float(h & 0xffff0000u);
    unsigned l;
    asm("cvt.rn.bf16x2.f32 %0, %1, %2;" : "=r"(l) : "f"(x1 - h1), "f"(x0 - h0));
    hi = h; lo = l;
}
__device__ __forceinline__ void mma16(float* c, const unsigned* a, const unsigned* b) {
    asm("mma.sync.aligned.m16n8k16.row.col.f32.bf16.bf16.f32 "
        "{%0,%1,%2,%3}, {%4,%5,%6,%7}, {%8,%9}, {%0,%1,%2,%3};"
        : "+f"(c[0]), "+f"(c[1]), "+f"(c[2]), "+f"(c[3])
        : "r"(a[0]), "r"(a[1]), "r"(a[2]), "r"(a[3]), "r"(b[0]), "r"(b[1]));
}
__device__ __forceinline__ void ldsm4(unsigned* r, uint32_t a) {
    asm volatile("ldmatrix.sync.aligned.m8n8.x4.shared.b16 {%0,%1,%2,%3}, [%4];"
                 : "=r"(r[0]), "=r"(r[1]), "=r"(r[2]), "=r"(r[3]) : "r"(a));
}
__device__ __forceinline__ void ldsm4t(unsigned* r, uint32_t a) {
    asm volatile("ldmatrix.sync.aligned.m8n8.x4.trans.shared.b16 {%0,%1,%2,%3}, [%4];"
                 : "=r"(r[0]), "=r"(r[1]), "=r"(r[2]), "=r"(r[3]) : "r"(a));
}
__device__ __forceinline__ float gelu_new(float x) {
    float z = GELU_C * (x + 0.044715f * x * x * x);
    float e = __expf(2.f * z);
    float th = (e - 1.f) / (e + 1.f);
    return 0.5f * x * (1.0f + th);
}

// ---------------------------------------------------------------------------
// GEMM (bf16x2 split, ldmatrix feeds): C = A@W + bias (+add) (+gelu).
// CTA 128x128, BK=32, double-buffered. 8 warps (2x4), warp tile 64x32.
// Smem per buffer (32KB): Ah[128m][32k] 8KB (row 64B, quad swz kq^(m&3)),
//   Al +8192, Bh[32k][128n] 8KB at +16384 (row 256B, quad swz nq^(k&7)), Bl +8192.
// A frags: LDSM.x4; B frags: LDSM.x4.trans (conflict-free).
// ---------------------------------------------------------------------------
#define G_SMEM 65536

__global__ __launch_bounds__(256) void gemm_tc(
    const float* __restrict__ A, const float* __restrict__ W,
    const float* __restrict__ bias, const float* __restrict__ add,
    float* __restrict__ C, int M, int N, int K, int fuse_gelu)
{
    extern __shared__ char smem[];
    const uint32_t sb = smem_u32(smem);
    const int tid = threadIdx.x, lane = tid & 31, warp = tid >> 5;
    const int wr = warp >> 2, wc = warp & 3;
    const int g = lane >> 2, tg = lane & 3;
    const int bm = blockIdx.y * 128, bn = blockIdx.x * 128;

    float acc[4][4][4];
    #pragma unroll
    for (int i = 0; i < 4; i++)
        #pragma unroll
        for (int j = 0; j < 4; j++)
            #pragma unroll
            for (int r = 0; r < 4; r++) acc[i][j][r] = 0.f;

    float ar[16], br[16];

    auto loadT = [&](int t) {
        const int k0 = t * 32;
        #pragma unroll
        for (int sl = 0; sl < 2; sl++) {
            const int s = tid + sl * 256;
            const int m = s >> 2, ko = (s & 3) * 8;
            const float* pa = A + (size_t)(bm + m) * K + k0 + ko;
            float4 u = *(const float4*)pa;
            float4 v = *(const float4*)(pa + 4);
            ar[sl * 8 + 0] = u.x; ar[sl * 8 + 1] = u.y; ar[sl * 8 + 2] = u.z; ar[sl * 8 + 3] = u.w;
            ar[sl * 8 + 4] = v.x; ar[sl * 8 + 5] = v.y; ar[sl * 8 + 6] = v.z; ar[sl * 8 + 7] = v.w;
            const int kb = s >> 4, nq = s & 15;
            const float* pw = W + (size_t)(k0 + kb) * N + bn + nq * 8;
            float4 x = *(const float4*)pw;
            float4 y = *(const float4*)(pw + 4);
            br[sl * 8 + 0] = x.x; br[sl * 8 + 1] = x.y; br[sl * 8 + 2] = x.z; br[sl * 8 + 3] = x.w;
            br[sl * 8 + 4] = y.x; br[sl * 8 + 5] = y.y; br[sl * 8 + 6] = y.z; br[sl * 8 + 7] = y.w;
        }
    };
    auto storeT = [&](int buf) {
        char* base = smem + buf * 32768;
        #pragma unroll
        for (int sl = 0; sl < 2; sl++) {
            const int s = tid + sl * 256;
            {
                const int m = s >> 2, kq = s & 3;
                unsigned h[4], l[4];
                #pragma unroll
                for (int e = 0; e < 4; e++)
                    bfsplit2(ar[sl * 8 + 2 * e], ar[sl * 8 + 2 * e + 1], h[e], l[e]);
                const uint32_t off = (uint32_t)(m * 64 + ((kq ^ (m & 3)) << 4));
                *(uint4*)(base + off)        = make_uint4(h[0], h[1], h[2], h[3]);
                *(uint4*)(base + 8192 + off) = make_uint4(l[0], l[1], l[2], l[3]);
            }
            {
                const int kb = s >> 4, nq = s & 15;
                unsigned h[4], l[4];
                #pragma unroll
                for (int e = 0; e < 4; e++)
                    bfsplit2(br[sl * 8 + 2 * e], br[sl * 8 + 2 * e + 1], h[e], l[e]);
                const uint32_t off = (uint32_t)(16384 + kb * 256 + ((nq ^ (kb & 7)) << 4));
                *(uint4*)(base + off)        = make_uint4(h[0], h[1], h[2], h[3]);
                *(uint4*)(base + 8192 + off) = make_uint4(l[0], l[1], l[2], l[3]);
            }
        }
    };
    auto compute = [&](int buf) {
        const uint32_t Ab = sb + buf * 32768;
        const uint32_t Bb = Ab + 16384;
        #pragma unroll
        for (int kk2 = 0; kk2 < 2; kk2++) {
            unsigned ah[4][4], al_[4][4];
            #pragma unroll
            for (int i = 0; i < 4; i++) {
                const int row = wr * 64 + i * 16 + (lane & 15);
                const int kq = kk2 * 2 + (lane >> 4);
                const uint32_t ad = Ab + row * 64 + ((kq ^ (row & 3)) << 4);
                ldsm4(ah[i], ad);
                ldsm4(al_[i], ad + 8192);
            }
            #pragma unroll
            for (int jp = 0; jp < 2; jp++) {
                const int k = kk2 * 16 + (lane & 15);
                const int ncol = wc * 32 + jp * 16 + ((lane >> 4) & 1) * 8;
                const uint32_t bd = Bb + k * 256 + (((ncol >> 3) ^ (k & 7)) << 4);
                unsigned bh[4], bl[4];
                ldsm4t(bh, bd);
                ldsm4t(bl, bd + 8192);
                #pragma unroll
                for (int sub = 0; sub < 2; sub++) {
                    const int jj = jp * 2 + sub;
                    #pragma unroll
                    for (int i = 0; i < 4; i++) {
                        mma16(acc[i][jj], ah[i],  bh + sub * 2);
                        mma16(acc[i][jj], ah[i],  bl + sub * 2);
                        mma16(acc[i][jj], al_[i], bh + sub * 2);
                    }
                }
            }
        }
    };

    const int T = K / 32;
    loadT(0); storeT(0); __syncthreads();
    for (int t = 0; t < T; t++) {
        if (t + 1 < T) loadT(t + 1);
        compute(t & 1);
        if (t + 1 < T) storeT((t + 1) & 1);
        __syncthreads();
    }

    #pragma unroll
    for (int i = 0; i < 4; i++) {
        int row0 = bm + wr * 64 + i * 16 + g;
        #pragma unroll
        for (int j = 0; j < 4; j++) {
            int col = bn + wc * 32 + j * 8 + 2 * tg;
            float2 bz = *(const float2*)(bias + col);
            float v0 = acc[i][j][0] + bz.x, v1 = acc[i][j][1] + bz.y;
            float v2 = acc[i][j][2] + bz.x, v3 = acc[i][j][3] + bz.y;
            if (add) {
                float2 a0 = *(const float2*)(add + (size_t)row0 * N + col);
                float2 a1 = *(const float2*)(add + (size_t)(row0 + 8) * N + col);
                v0 += a0.x; v1 += a0.y; v2 += a1.x; v3 += a1.y;
            }
            if (fuse_gelu) {
                v0 = gelu_new(v0); v1 = gelu_new(v1);
                v2 = gelu_new(v2); v3 = gelu_new(v3);
            }
            *(float2*)(C + (size_t)row0 * N + col) = make_float2(v0, v1);
            *(float2*)(C + (size_t)(row0 + 8) * N + col) = make_float2(v2, v3);
        }
    }
}

// ---------------------------------------------------------------------------
// FlashAttention (bf16x2 split, m16n8k16) — unchanged from R11.
// ---------------------------------------------------------------------------
#define LDQ 36
#define LDK 72
#define LDV 72
#define ATTN_SMEM ((2 * 128 * LDQ + 2 * 32 * LDK + 2 * 32 * LDV) * 4 + Sc * 4)

__global__ __launch_bounds__(256) void attn_tc(
    const float* __restrict__ Q, const float* __restrict__ Kin,
    const float* __restrict__ Vin, const int* __restrict__ mask,
    float* __restrict__ O)
{
    extern __shared__ unsigned sm_a[];
    unsigned* Qh = sm_a;
    unsigned* Ql = Qh + 128 * LDQ;
    unsigned* Kh = Ql + 128 * LDQ;
    unsigned* Kl = Kh + 32 * LDK;
    unsigned* Vh = Kl + 32 * LDK;
    unsigned* Vl = Vh + 32 * LDV;
    float* madd = (float*)(Vl + 32 * LDV);

    const int tid = threadIdx.x, lane = tid & 31, warp = tid >> 5;
    const int g = lane >> 2, tg = lane & 3;
    const int qt = blockIdx.x & 3;
    const int n  = (blockIdx.x >> 2) & 15;
    const int b  = blockIdx.x >> 6;

    for (int j = tid; j < Sc; j += 256)
        madd[j] = mask[b * Sc + j] ? 0.f : -10000.f;

    {
        int r = tid >> 1, d0 = (tid & 1) * 32;
        const float* qp = Q + (size_t)(b * Sc + qt * 128 + r) * Hc + n * Dc + d0;
        #pragma unroll
        for (int i = 0; i < 32; i += 8) {
            float4 u = *(const float4*)(qp + i);
            float4 w = *(const float4*)(qp + i + 4);
            unsigned h0, l0, h1, l1, h2, l2, h3, l3;
            bfsplit2(u.x, u.y, h0, l0); bfsplit2(u.z, u.w, h1, l1);
            bfsplit2(w.x, w.y, h2, l2); bfsplit2(w.z, w.w, h3, l3);
            *(uint4*)&Qh[r * LDQ + ((d0 + i) >> 1)] = make_uint4(h0, h1, h2, h3);
            *(uint4*)&Ql[r * LDQ + ((d0 + i) >> 1)] = make_uint4(l0, l1, l2, l3);
        }
    }
    __syncthreads();

    float o[8][4];
    #pragma unroll
    for (int j = 0; j < 8; j++)
        #pragma unroll
        for (int r = 0; r < 4; r++) o[j][r] = 0.f;
    float m_run[2] = {-1e30f, -1e30f};
    float l_run[2] = {0.f, 0.f};

    for (int kv = 0; kv < Sc; kv += 64) {
        {
            int r = tid >> 2, d0 = (tid & 3) * 16;
            const float* kpp = Kin + (size_t)(b * Sc + kv + r) * Hc + n * Dc + d0;
            float4 u = *(const float4*)(kpp);
            float4 w = *(const float4*)(kpp + 4);
            float4 x = *(const float4*)(kpp + 8);
            float4 y = *(const float4*)(kpp + 12);
            float pv[16] = {u.x, u.y, u.z, u.w, w.x, w.y, w.z, w.w,
                            x.x, x.y, x.z, x.w, y.x, y.y, y.z, y.w};
            #pragma unroll
            for (int p = 0; p < 8; p++) {
                unsigned h, l;
                bfsplit2(pv[2 * p], pv[2 * p + 1], h, l);
                Kh[((d0 >> 1) + p) * LDK + r] = h;
                Kl[((d0 >> 1) + p) * LDK + r] = l;
            }
            int kp2 = tid >> 3, dv0 = (tid & 7) * 8;
            const float* v0p = Vin + (size_t)(b * Sc + kv + 2 * kp2) * Hc + n * Dc + dv0;
            float4 a0 = *(const float4*)(v0p);
            float4 a1 = *(const float4*)(v0p + 4);
            float4 b0 = *(const float4*)(v0p + Hc);
            float4 b1 = *(const float4*)(v0p + Hc + 4);
            unsigned hh[8], ll[8];
            bfsplit2(a0.x, b0.x, hh[0], ll[0]); bfsplit2(a0.y, b0.y, hh[1], ll[1]);
            bfsplit2(a0.z, b0.z, hh[2], ll[2]); bfsplit2(a0.w, b0.w, hh[3], ll[3]);
            bfsplit2(a1.x, b1.x, hh[4], ll[4]); bfsplit2(a1.y, b1.y, hh[5], ll[5]);
            bfsplit2(a1.z, b1.z, hh[6], ll[6]); bfsplit2(a1.w, b1.w, hh[7], ll[7]);
            *(uint4*)&Vh[kp2 * LDV + dv0]     = make_uint4(hh[0], hh[1], hh[2], hh[3]);
            *(uint4*)&Vh[kp2 * LDV + dv0 + 4] = make_uint4(hh[4], hh[5], hh[6], hh[7]);
            *(uint4*)&Vl[kp2 * LDV + dv0]     = make_uint4(ll[0], ll[1], ll[2], ll[3]);
            *(uint4*)&Vl[kp2 * LDV + dv0 + 4] = make_uint4(ll[4], ll[5], ll[6], ll[7]);
        }
        __syncthreads();

        float s[8][4];
        #pragma unroll
        for (int j = 0; j < 8; j++)
            #pragma unroll
            for (int r = 0; r < 4; r++) s[j][r] = 0.f;
        #pragma unroll
        for (int kk2 = 0; kk2 < 32; kk2 += 8) {
            int rb = warp * 16 + g;
            unsigned qh[4], ql_[4];
            qh[0] = Qh[rb * LDQ + kk2 + tg];        qh[1] = Qh[(rb + 8) * LDQ + kk2 + tg];
            qh[2] = Qh[rb * LDQ + kk2 + tg + 4];    qh[3] = Qh[(rb + 8) * LDQ + kk2 + tg + 4];
            ql_[0] = Ql[rb * LDQ + kk2 + tg];       ql_[1] = Ql[(rb + 8) * LDQ + kk2 + tg];
            ql_[2] = Ql[rb * LDQ + kk2 + tg + 4];   ql_[3] = Ql[(rb + 8) * LDQ + kk2 + tg + 4];
            #pragma unroll
            for (int j = 0; j < 8; j++) {
                unsigned kh2[2], kl2[2];
                kh2[0] = Kh[(kk2 + tg) * LDK + j * 8 + g];
                kh2[1] = Kh[(kk2 + tg + 4) * LDK + j * 8 + g];
                kl2[0] = Kl[(kk2 + tg) * LDK + j * 8 + g];
                kl2[1] = Kl[(kk2 + tg + 4) * LDK + j * 8 + g];
                mma16(s[j], qh, kh2);
                mma16(s[j], qh, kl2);
                mma16(s[j], ql_, kh2);
            }
        }

        float corr[2];
        #pragma unroll
        for (int r2 = 0; r2 < 2; r2++) {
            float mx = m_run[r2];
            #pragma unroll
            for (int j = 0; j < 8; j++)
                #pragma unroll
                for (int c = 0; c < 2; c++) {
                    float val = s[j][r2 * 2 + c] * 0.125f + madd[kv + j * 8 + 2 * tg + c];
                    s[j][r2 * 2 + c] = val;
                    mx = fmaxf(mx, val);
                }
            mx = fmaxf(mx, __shfl_xor_sync(0xffffffffu, mx, 1));
            mx = fmaxf(mx, __shfl_xor_sync(0xffffffffu, mx, 2));
            corr[r2] = __expf(m_run[r2] - mx);
            m_run[r2] = mx;
            float rs = 0.f;
            #pragma unroll
            for (int j = 0; j < 8; j++)
                #pragma unroll
                for (int c = 0; c < 2; c++) {
                    float e = __expf(s[j][r2 * 2 + c] - mx);
                    s[j][r2 * 2 + c] = e;
                    rs += e;
                }
            rs += __shfl_xor_sync(0xffffffffu, rs, 1);
            rs += __shfl_xor_sync(0xffffffffu, rs, 2);
            l_run[r2] = l_run[r2] * corr[r2] + rs;
        }
        #pragma unroll
        for (int j = 0; j < 8; j++) {
            o[j][0] *= corr[0]; o[j][1] *= corr[0];
            o[j][2] *= corr[1]; o[j][3] *= corr[1];
        }

        #pragma unroll
        for (int kf = 0; kf < 4; kf++) {
            unsigned ph[4], pl[4];
            bfsplit2(s[2 * kf][0],     s[2 * kf][1],     ph[0], pl[0]);
            bfsplit2(s[2 * kf][2],     s[2 * kf][3],     ph[1], pl[1]);
            bfsplit2(s[2 * kf + 1][0], s[2 * kf + 1][1], ph[2], pl[2]);
            bfsplit2(s[2 * kf + 1][2], s[2 * kf + 1][3], ph[3], pl[3]);
            #pragma unroll
            for (int j = 0; j < 8; j++) {
                unsigned vh2[2], vl2[2];
                vh2[0] = Vh[(kf * 8 + tg) * LDV + j * 8 + g];
                vh2[1] = Vh[(kf * 8 + tg + 4) * LDV + j * 8 + g];
                vl2[0] = Vl[(kf * 8 + tg) * LDV + j * 8 + g];
                vl2[1] = Vl[(kf * 8 + tg + 4) * LDV + j * 8 + g];
                mma16(o[j], ph, vh2);
                mma16(o[j], ph, vl2);
                mma16(o[j], pl, vh2);
            }
        }
        __syncthreads();
    }

    float inv0 = 1.f / l_run[0], inv1 = 1.f / l_run[1];
    int row0 = b * Sc + qt * 128 + warp * 16 + g;
    #pragma unroll
    for (int j = 0; j < 8; j++) {
        int col = n * Dc + j * 8 + 2 * tg;
        *(float2*)(O + (size_t)row0 * Hc + col) =
            make_float2(o[j][0] * inv0, o[j][1] * inv0);
        *(float2*)(O + (size_t)(row0 + 8) * Hc + col) =
            make_float2(o[j][2] * inv1, o[j][3] * inv1);
    }
}

// ---------------------------------------------------------------------------
// LayerNorm over H=1024
// ---------------------------------------------------------------------------
__device__ __forceinline__ float block_sum_256(float v) {
    __shared__ float sh[8];
    #pragma unroll
    for (int o = 16; o > 0; o >>= 1) v += __shfl_xor_sync(0xffffffffu, v, o);
    __syncthreads();
    if ((threadIdx.x & 31) == 0) sh[threadIdx.x >> 5] = v;
    __syncthreads();
    float t = sh[0];
    #pragma unroll
    for (int i = 1; i < 8; i++) t += sh[i];
    return t;
}

__global__ __launch_bounds__(256) void ln_kernel(
    const float* __restrict__ x, const float* __restrict__ ln,
    float* __restrict__ out)
{
    const int row = blockIdx.x, tid = threadIdx.x;
    const float* xr = x + (size_t)row * Hc;
    float v[4], s = 0.f;
    #pragma unroll
    for (int i = 0; i < 4; i++) { v[i] = xr[tid + 256 * i]; s += v[i]; }
    s = block_sum_256(s);
    const float mean = s * (1.f / Hc);
    float q = 0.f;
    #pragma unroll
    for (int i = 0; i < 4; i++) { float d = v[i] - mean; q += d * d; }
    q = block_sum_256(q);
    const float inv = rsqrtf(q * (1.f / Hc) + LN_EPS);
    #pragma unroll
    for (int i = 0; i < 4; i++) {
        int c = tid + 256 * i;
        out[(size_t)row * Hc + c] = (v[i] - mean) * inv * ln[c] + ln[Hc + c];
    }
}

// ---------------------------------------------------------------------------
// Orchestration
// ---------------------------------------------------------------------------
extern "C" void kernel_launch(void* const* d_in, const int* in_sizes, int n_in,
                              void* d_out, int out_size)
{
    const float* hidden   = (const float*)d_in[0];
    const float* enc      = (const float*)d_in[1];
    const int*   amask    = (const int*)d_in[2];
    const int*   emask    = (const int*)d_in[3];
    const float* sa_qkv_w = (const float*)d_in[4];
    const float* sa_qkv_b = (const float*)d_in[5];
    const float* sa_out_w = (const float*)d_in[6];
    const float* sa_out_b = (const float*)d_in[7];
    const float* sa_ln    = (const float*)d_in[8];
    const float* ca_qkv_w = (const float*)d_in[9];
    const float* ca_qkv_b = (const float*)d_in[10];
    const float* ca_out_w = (const float*)d_in[11];
    const float* ca_out_b = (const float*)d_in[12];
    const float* ca_ln    = (const float*)d_in[13];
    const float* o1_w     = (const float*)d_in[14];
    const float* o1_b     = (const float*)d_in[15];
    const float* o1_ln    = (const float*)d_in[16];
    const float* ffn_w    = (const float*)d_in[17];
    const float* ffn_b    = (const float*)d_in[18];
    const float* o2_w     = (const float*)d_in[19];
    const float* o2_b     = (const float*)d_in[20];
    const float* o2_ln    = (const float*)d_in[21];
    float* out = (float*)d_out;

    cudaFuncSetAttribute(gemm_tc, cudaFuncAttributeMaxDynamicSharedMemorySize, G_SMEM);
    cudaFuncSetAttribute(attn_tc, cudaFuncAttributeMaxDynamicSharedMemorySize, ATTN_SMEM);

    float *h, *q, *k, *v, *a, *t, *x1, *x2, *x3, *inter;
    cudaGetSymbolAddress((void**)&h,  g_h);
    cudaGetSymbolAddress((void**)&q,  g_q);
    cudaGetSymbolAddress((void**)&k,  g_k);
    cudaGetSymbolAddress((void**)&v,  g_v);
    cudaGetSymbolAddress((void**)&a,  g_a);
    cudaGetSymbolAddress((void**)&t,  g_t);
    cudaGetSymbolAddress((void**)&x1, g_x1);
    cudaGetSymbolAddress((void**)&x2, g_x2);
    cudaGetSymbolAddress((void**)&x3, g_x3);
    cudaGetSymbolAddress((void**)&inter, g_inter);

    cudaMemcpyAsync(h, hidden, (size_t)Mrows * Hc * sizeof(float),
                    cudaMemcpyDeviceToDevice, 0);

    const dim3 g1(Hc / 128, Mrows / 128);
    const dim3 gF(Fc / 128, Mrows / 128);
    const int attnBlocks = Bc * NHc * (Sc / 128);

    for (int i = 0; i < LAYERS; i++) {
        const float* W  = sa_qkv_w + (size_t)i * 3 * Hc * Hc;
        const float* Bb = sa_qkv_b + (size_t)i * 3 * Hc;
        gemm_tc<<<g1, 256, G_SMEM>>>(h, W,               Bb,          nullptr, q, Mrows, Hc, Hc, 0);
        gemm_tc<<<g1, 256, G_SMEM>>>(h, W + Hc * Hc,     Bb + Hc,     nullptr, k, Mrows, Hc, Hc, 0);
        gemm_tc<<<g1, 256, G_SMEM>>>(h, W + 2 * Hc * Hc, Bb + 2 * Hc, nullptr, v, Mrows, Hc, Hc, 0);
        attn_tc<<<attnBlocks, 256, ATTN_SMEM>>>(q, k, v, amask, a);
        gemm_tc<<<g1, 256, G_SMEM>>>(a, sa_out_w + (size_t)i * Hc * Hc, sa_out_b + i * Hc, h, t,
                                     Mrows, Hc, Hc, 0);
        ln_kernel<<<Mrows, 256>>>(t, sa_ln + (size_t)i * 2 * Hc, x1);

        const float* Wc  = ca_qkv_w + (size_t)i * 3 * Hc * Hc;
        const float* Bbc = ca_qkv_b + (size_t)i * 3 * Hc;
        gemm_tc<<<g1, 256, G_SMEM>>>(h,   Wc,               Bbc,          nullptr, q, Mrows, Hc, Hc, 0);
        gemm_tc<<<g1, 256, G_SMEM>>>(enc, Wc + Hc * Hc,     Bbc + Hc,     nullptr, k, Mrows, Hc, Hc, 0);
        gemm_tc<<<g1, 256, G_SMEM>>>(enc, Wc + 2 * Hc * Hc, Bbc + 2 * Hc, nullptr, v, Mrows, Hc, Hc, 0);
        attn_tc<<<attnBlocks, 256, ATTN_SMEM>>>(q, k, v, emask, a);
        gemm_tc<<<g1, 256, G_SMEM>>>(a, ca_out_w + (size_t)i * Hc * Hc, ca_out_b + i * Hc, h, t,
                                     Mrows, Hc, Hc, 0);
        ln_kernel<<<Mrows, 256>>>(t, ca_ln + (size_t)i * 2 * Hc, x2);

        gemm_tc<<<g1, 256, G_SMEM>>>(x1, o1_w + (size_t)i * Hc * Hc, o1_b + i * Hc, x2, t,
                                     Mrows, Hc, Hc, 0);
        ln_kernel<<<Mrows, 256>>>(t, o1_ln + (size_t)i * 2 * Hc, x3);

        gemm_tc<<<gF, 256, G_SMEM>>>(x3, ffn_w + (size_t)i * Hc * Fc, ffn_b + (size_t)i * Fc,
                                     nullptr, inter, Mrows, Fc, Hc, 1);
        gemm_tc<<<g1, 256, G_SMEM>>>(inter, o2_w + (size_t)i * Fc * Hc, o2_b + i * Hc, x3, t,
                                     Mrows, Hc, Fc, 0);
        ln_kernel<<<Mrows, 256>>>(t, o2_ln + (size_t)i * 2 * Hc,
                                  (i == LAYERS - 1) ? out : h);
    }
}

// round 14
// speedup vs baseline: 1.5682x; 1.5682x over previous
#include <cuda_runtime.h>
#include <cuda_bf16.h>
#include <math.h>
#include <stdint.h>

#define LAYERS 6
#define Hc 1024
#define NHc 16
#define Dc 64
#define Fc 4096
#define Bc 4
#define Sc 512
#define Mrows (Bc * Sc)
#define LN_EPS 1e-12f
#define GELU_C 0.7978845608028654f

// fp32 scratch
__device__ float g_h[Mrows * Hc];
__device__ float g_q[Mrows * Hc];
__device__ float g_k[Mrows * Hc];
__device__ float g_v[Mrows * Hc];
__device__ float g_t[Mrows * Hc];
__device__ float g_x2[Mrows * Hc];
__device__ float g_x3[Mrows * Hc];

// pre-split weight arenas (hi/lo bf16x2 words, pairs along K)
#define WARENA (53477376ULL)
__device__ unsigned g_whi[WARENA];
__device__ unsigned g_wlo[WARENA];

// pre-split activation word buffers [M][K/2]
__device__ unsigned g_hs_hi[Mrows * Hc / 2],  g_hs_lo[Mrows * Hc / 2];
__device__ unsigned g_es_hi[Mrows * Hc / 2],  g_es_lo[Mrows * Hc / 2];
__device__ unsigned g_as_hi[Mrows * Hc / 2],  g_as_lo[Mrows * Hc / 2];
__device__ unsigned g_x1_hi[Mrows * Hc / 2],  g_x1_lo[Mrows * Hc / 2];
__device__ unsigned g_x3_hi[Mrows * Hc / 2],  g_x3_lo[Mrows * Hc / 2];
__device__ unsigned g_in_hi[Mrows * Fc / 2],  g_in_lo[Mrows * Fc / 2];

// ---------------------------------------------------------------------------
// Helpers
// ---------------------------------------------------------------------------
__device__ __forceinline__ uint32_t smem_u32(const void* p) {
    uint32_t a;
    asm("{ .reg .u64 t; cvta.to.shared.u64 t, %1; cvt.u32.u64 %0, t; }" : "=r"(a) : "l"(p));
    return a;
}
// bf16 hi/lo split: x = hi + lo, packed bf16x2 (x0 low half, x1 high half)
__device__ __forceinline__ void bfsplit2(float x0, float x1, unsigned& hi, unsigned& lo) {
    unsigned h;
    asm("cvt.rn.bf16x2.f32 %0, %1, %2;" : "=r"(h) : "f"(x1), "f"(x0));
    float h0 = __uint_as_float(h << 16);
    float h1 = __uint_as_float(h & 0xffff0000u);
    unsigned l;
    asm("cvt.rn.bf16x2.f32 %0, %1, %2;" : "=r"(l) : "f"(x1 - h1), "f"(x0 - h0));
    hi = h; lo = l;
}
__device__ __forceinline__ void mma16(float* c, const unsigned* a, const unsigned* b) {
    asm("mma.sync.aligned.m16n8k16.row.col.f32.bf16.bf16.f32 "
        "{%0,%1,%2,%3}, {%4,%5,%6,%7}, {%8,%9}, {%0,%1,%2,%3};"
        : "+f"(c[0]), "+f"(c[1]), "+f"(c[2]), "+f"(c[3])
        : "r"(a[0]), "r"(a[1]), "r"(a[2]), "r"(a[3]), "r"(b[0]), "r"(b[1]));
}
__device__ __forceinline__ void cp16(uint32_t dst, const void* src) {
    asm volatile("cp.async.cg.shared.global [%0], [%1], 16;" :: "r"(dst), "l"(src));
}
__device__ __forceinline__ float gelu_new(float x) {
    float z = GELU_C * (x + 0.044715f * x * x * x);
    float e = __expf(2.f * z);
    float th = (e - 1.f) / (e + 1.f);
    return 0.5f * x * (1.0f + th);
}

// ---------------------------------------------------------------------------
// Split kernels
// ---------------------------------------------------------------------------
// weights: src fp32 [2*K2][N] -> hi/lo word arrays [K2][N], pair rows (2k2, 2k2+1)
__global__ __launch_bounds__(256) void split_w(
    const float* __restrict__ src, unsigned* __restrict__ hi,
    unsigned* __restrict__ lo, int K2, int N)
{
    int idx = blockIdx.x * 256 + threadIdx.x;
    if (idx >= K2 * N) return;
    int k2 = idx / N, n = idx - k2 * N;
    float f0 = src[(size_t)(2 * k2) * N + n];
    float f1 = src[(size_t)(2 * k2 + 1) * N + n];
    unsigned h, l;
    bfsplit2(f0, f1, h, l);
    hi[idx] = h; lo[idx] = l;
}
// activations: row-major contiguous pairs along last dim
__global__ __launch_bounds__(256) void split_act(
    const float2* __restrict__ src, unsigned* __restrict__ hi,
    unsigned* __restrict__ lo, int total)
{
    int idx = blockIdx.x * 256 + threadIdx.x;
    if (idx >= total) return;
    float2 f = src[idx];
    unsigned h, l;
    bfsplit2(f.x, f.y, h, l);
    hi[idx] = h; lo[idx] = l;
}

// ---------------------------------------------------------------------------
// GEMM on pre-split operands. CTA 128x128, BK=16 word-pairs (8 words),
// 3-stage cp.async pipeline. 8 warps (2x4), warp tile 64x32 (R11 schedule).
// Stage layout (words): Ahi[128][12] 0..1535 | Alo 1536.. | Bhi[8][136] @3072 |
// Blo @4160; stage = 5248 words = 20992 B; 3 stages = 62976 B.
// ---------------------------------------------------------------------------
#define STG_W 5248
#define STG_B 20992
#define G_SMEM (3 * STG_B)

__global__ __launch_bounds__(256, 2) void gemm_ps(
    const unsigned* __restrict__ Ahi, const unsigned* __restrict__ Alo,
    const unsigned* __restrict__ Whi, const unsigned* __restrict__ Wlo,
    const float* __restrict__ bias, const float* __restrict__ add,
    float* __restrict__ C, unsigned* __restrict__ Chi, unsigned* __restrict__ Clo,
    int M, int N, int K, int fuse_gelu)
{
    extern __shared__ char smem[];
    unsigned* sw = (unsigned*)smem;
    const uint32_t sb = smem_u32(smem);
    const int tid = threadIdx.x, lane = tid & 31, warp = tid >> 5;
    const int wr = warp >> 2, wc = warp & 3;
    const int g = lane >> 2, tg = lane & 3;
    const int bm = blockIdx.y * 128, bn = blockIdx.x * 128;
    const int K2 = K >> 1;

    // cp.async assignments
    const int arow = tid >> 1, ahalf = tid & 1;        // A: 2 chunks/row
    const int br_ = tid >> 5, bc_ = tid & 31;          // B: 32 chunks/row x 8 rows

    float acc[4][4][4];
    #pragma unroll
    for (int i = 0; i < 4; i++)
        #pragma unroll
        for (int j = 0; j < 4; j++)
            #pragma unroll
            for (int r = 0; r < 4; r++) acc[i][j][r] = 0.f;

    auto issue = [&](int t) {
        const uint32_t st = sb + (uint32_t)(t % 3) * STG_B;
        const unsigned* gA = Ahi + (size_t)(bm + arow) * K2 + t * 8 + ahalf * 4;
        const unsigned* gAl = Alo + (size_t)(bm + arow) * K2 + t * 8 + ahalf * 4;
        cp16(st + arow * 48 + ahalf * 16, gA);
        cp16(st + 6144 + arow * 48 + ahalf * 16, gAl);
        const size_t wo = (size_t)(t * 8 + br_) * N + bn + bc_ * 4;
        cp16(st + 12288 + br_ * 544 + bc_ * 16, Whi + wo);
        cp16(st + 16640 + br_ * 544 + bc_ * 16, Wlo + wo);
        asm volatile("cp.async.commit_group;" ::: "memory");
    };
    auto compute = [&](int t) {
        const unsigned* S = sw + (size_t)(t % 3) * STG_W;
        unsigned ah[4][4], al_[4][4];
        #pragma unroll
        for (int i = 0; i < 4; i++) {
            const int rb = wr * 64 + i * 16 + g;
            ah[i][0]  = S[rb * 12 + tg];        ah[i][1]  = S[(rb + 8) * 12 + tg];
            ah[i][2]  = S[rb * 12 + tg + 4];    ah[i][3]  = S[(rb + 8) * 12 + tg + 4];
            al_[i][0] = S[1536 + rb * 12 + tg];      al_[i][1] = S[1536 + (rb + 8) * 12 + tg];
            al_[i][2] = S[1536 + rb * 12 + tg + 4];  al_[i][3] = S[1536 + (rb + 8) * 12 + tg + 4];
        }
        #pragma unroll
        for (int j = 0; j < 4; j++) {
            const int cb = wc * 32 + j * 8 + g;
            unsigned bh2[2], bl2[2];
            bh2[0] = S[3072 + tg * 136 + cb];       bh2[1] = S[3072 + (tg + 4) * 136 + cb];
            bl2[0] = S[4160 + tg * 136 + cb];       bl2[1] = S[4160 + (tg + 4) * 136 + cb];
            #pragma unroll
            for (int i = 0; i < 4; i++) {
                mma16(acc[i][j], ah[i],  bh2);
                mma16(acc[i][j], ah[i],  bl2);
                mma16(acc[i][j], al_[i], bh2);
            }
        }
    };

    const int T = K / 16;
    issue(0);
    if (T > 1) issue(1);
    for (int t = 0; t < T; t++) {
        asm volatile("cp.async.wait_group 1;" ::: "memory");
        __syncthreads();
        compute(t);
        if (t + 2 < T) issue(t + 2);
        else asm volatile("cp.async.commit_group;" ::: "memory");
        __syncthreads();
    }

    #pragma unroll
    for (int i = 0; i < 4; i++) {
        int row0 = bm + wr * 64 + i * 16 + g;
        #pragma unroll
        for (int j = 0; j < 4; j++) {
            int col = bn + wc * 32 + j * 8 + 2 * tg;
            float2 bz = *(const float2*)(bias + col);
            float v0 = acc[i][j][0] + bz.x, v1 = acc[i][j][1] + bz.y;
            float v2 = acc[i][j][2] + bz.x, v3 = acc[i][j][3] + bz.y;
            if (add) {
                float2 a0 = *(const float2*)(add + (size_t)row0 * N + col);
                float2 a1 = *(const float2*)(add + (size_t)(row0 + 8) * N + col);
                v0 += a0.x; v1 += a0.y; v2 += a1.x; v3 += a1.y;
            }
            if (fuse_gelu) {
                v0 = gelu_new(v0); v1 = gelu_new(v1);
                v2 = gelu_new(v2); v3 = gelu_new(v3);
            }
            if (C) {
                *(float2*)(C + (size_t)row0 * N + col) = make_float2(v0, v1);
                *(float2*)(C + (size_t)(row0 + 8) * N + col) = make_float2(v2, v3);
            }
            if (Chi) {
                unsigned h0, l0, h1, l1;
                bfsplit2(v0, v1, h0, l0);
                bfsplit2(v2, v3, h1, l1);
                size_t w0 = (size_t)row0 * (N >> 1) + (col >> 1);
                size_t w1 = (size_t)(row0 + 8) * (N >> 1) + (col >> 1);
                Chi[w0] = h0; Clo[w0] = l0;
                Chi[w1] = h1; Clo[w1] = l1;
            }
        }
    }
}

// ---------------------------------------------------------------------------
// FlashAttention (bf16x2 split, m16n8k16) — R11 core; epilogue writes split.
// ---------------------------------------------------------------------------
#define LDQ 36
#define LDK 72
#define LDV 72
#define ATTN_SMEM ((2 * 128 * LDQ + 2 * 32 * LDK + 2 * 32 * LDV) * 4 + Sc * 4)

__global__ __launch_bounds__(256) void attn_tc(
    const float* __restrict__ Q, const float* __restrict__ Kin,
    const float* __restrict__ Vin, const int* __restrict__ mask,
    unsigned* __restrict__ Ohi, unsigned* __restrict__ Olo)
{
    extern __shared__ unsigned sm_a[];
    unsigned* Qh = sm_a;
    unsigned* Ql = Qh + 128 * LDQ;
    unsigned* Kh = Ql + 128 * LDQ;
    unsigned* Kl = Kh + 32 * LDK;
    unsigned* Vh = Kl + 32 * LDK;
    unsigned* Vl = Vh + 32 * LDV;
    float* madd = (float*)(Vl + 32 * LDV);

    const int tid = threadIdx.x, lane = tid & 31, warp = tid >> 5;
    const int g = lane >> 2, tg = lane & 3;
    const int qt = blockIdx.x & 3;
    const int n  = (blockIdx.x >> 2) & 15;
    const int b  = blockIdx.x >> 6;

    for (int j = tid; j < Sc; j += 256)
        madd[j] = mask[b * Sc + j] ? 0.f : -10000.f;

    {
        int r = tid >> 1, d0 = (tid & 1) * 32;
        const float* qp = Q + (size_t)(b * Sc + qt * 128 + r) * Hc + n * Dc + d0;
        #pragma unroll
        for (int i = 0; i < 32; i += 8) {
            float4 u = *(const float4*)(qp + i);
            float4 w = *(const float4*)(qp + i + 4);
            unsigned h0, l0, h1, l1, h2, l2, h3, l3;
            bfsplit2(u.x, u.y, h0, l0); bfsplit2(u.z, u.w, h1, l1);
            bfsplit2(w.x, w.y, h2, l2); bfsplit2(w.z, w.w, h3, l3);
            *(uint4*)&Qh[r * LDQ + ((d0 + i) >> 1)] = make_uint4(h0, h1, h2, h3);
            *(uint4*)&Ql[r * LDQ + ((d0 + i) >> 1)] = make_uint4(l0, l1, l2, l3);
        }
    }
    __syncthreads();

    float o[8][4];
    #pragma unroll
    for (int j = 0; j < 8; j++)
        #pragma unroll
        for (int r = 0; r < 4; r++) o[j][r] = 0.f;
    float m_run[2] = {-1e30f, -1e30f};
    float l_run[2] = {0.f, 0.f};

    for (int kv = 0; kv < Sc; kv += 64) {
        {
            int r = tid >> 2, d0 = (tid & 3) * 16;
            const float* kpp = Kin + (size_t)(b * Sc + kv + r) * Hc + n * Dc + d0;
            float4 u = *(const float4*)(kpp);
            float4 w = *(const float4*)(kpp + 4);
            float4 x = *(const float4*)(kpp + 8);
            float4 y = *(const float4*)(kpp + 12);
            float pv[16] = {u.x, u.y, u.z, u.w, w.x, w.y, w.z, w.w,
                            x.x, x.y, x.z, x.w, y.x, y.y, y.z, y.w};
            #pragma unroll
            for (int p = 0; p < 8; p++) {
                unsigned h, l;
                bfsplit2(pv[2 * p], pv[2 * p + 1], h, l);
                Kh[((d0 >> 1) + p) * LDK + r] = h;
                Kl[((d0 >> 1) + p) * LDK + r] = l;
            }
            int kp2 = tid >> 3, dv0 = (tid & 7) * 8;
            const float* v0p = Vin + (size_t)(b * Sc + kv + 2 * kp2) * Hc + n * Dc + dv0;
            float4 a0 = *(const float4*)(v0p);
            float4 a1 = *(const float4*)(v0p + 4);
            float4 b0 = *(const float4*)(v0p + Hc);
            float4 b1 = *(const float4*)(v0p + Hc + 4);
            unsigned hh[8], ll[8];
            bfsplit2(a0.x, b0.x, hh[0], ll[0]); bfsplit2(a0.y, b0.y, hh[1], ll[1]);
            bfsplit2(a0.z, b0.z, hh[2], ll[2]); bfsplit2(a0.w, b0.w, hh[3], ll[3]);
            bfsplit2(a1.x, b1.x, hh[4], ll[4]); bfsplit2(a1.y, b1.y, hh[5], ll[5]);
            bfsplit2(a1.z, b1.z, hh[6], ll[6]); bfsplit2(a1.w, b1.w, hh[7], ll[7]);
            *(uint4*)&Vh[kp2 * LDV + dv0]     = make_uint4(hh[0], hh[1], hh[2], hh[3]);
            *(uint4*)&Vh[kp2 * LDV + dv0 + 4] = make_uint4(hh[4], hh[5], hh[6], hh[7]);
            *(uint4*)&Vl[kp2 * LDV + dv0]     = make_uint4(ll[0], ll[1], ll[2], ll[3]);
            *(uint4*)&Vl[kp2 * LDV + dv0 + 4] = make_uint4(ll[4], ll[5], ll[6], ll[7]);
        }
        __syncthreads();

        float s[8][4];
        #pragma unroll
        for (int j = 0; j < 8; j++)
            #pragma unroll
            for (int r = 0; r < 4; r++) s[j][r] = 0.f;
        #pragma unroll
        for (int kk2 = 0; kk2 < 32; kk2 += 8) {
            int rb = warp * 16 + g;
            unsigned qh[4], ql_[4];
            qh[0] = Qh[rb * LDQ + kk2 + tg];        qh[1] = Qh[(rb + 8) * LDQ + kk2 + tg];
            qh[2] = Qh[rb * LDQ + kk2 + tg + 4];    qh[3] = Qh[(rb + 8) * LDQ + kk2 + tg + 4];
            ql_[0] = Ql[rb * LDQ + kk2 + tg];       ql_[1] = Ql[(rb + 8) * LDQ + kk2 + tg];
            ql_[2] = Ql[rb * LDQ + kk2 + tg + 4];   ql_[3] = Ql[(rb + 8) * LDQ + kk2 + tg + 4];
            #pragma unroll
            for (int j = 0; j < 8; j++) {
                unsigned kh2[2], kl2[2];
                kh2[0] = Kh[(kk2 + tg) * LDK + j * 8 + g];
                kh2[1] = Kh[(kk2 + tg + 4) * LDK + j * 8 + g];
                kl2[0] = Kl[(kk2 + tg) * LDK + j * 8 + g];
                kl2[1] = Kl[(kk2 + tg + 4) * LDK + j * 8 + g];
                mma16(s[j], qh, kh2);
                mma16(s[j], qh, kl2);
                mma16(s[j], ql_, kh2);
            }
        }

        float corr[2];
        #pragma unroll
        for (int r2 = 0; r2 < 2; r2++) {
            float mx = m_run[r2];
            #pragma unroll
            for (int j = 0; j < 8; j++)
                #pragma unroll
                for (int c = 0; c < 2; c++) {
                    float val = s[j][r2 * 2 + c] * 0.125f + madd[kv + j * 8 + 2 * tg + c];
                    s[j][r2 * 2 + c] = val;
                    mx = fmaxf(mx, val);
                }
            mx = fmaxf(mx, __shfl_xor_sync(0xffffffffu, mx, 1));
            mx = fmaxf(mx, __shfl_xor_sync(0xffffffffu, mx, 2));
            corr[r2] = __expf(m_run[r2] - mx);
            m_run[r2] = mx;
            float rs = 0.f;
            #pragma unroll
            for (int j = 0; j < 8; j++)
                #pragma unroll
                for (int c = 0; c < 2; c++) {
                    float e = __expf(s[j][r2 * 2 + c] - mx);
                    s[j][r2 * 2 + c] = e;
                    rs += e;
                }
            rs += __shfl_xor_sync(0xffffffffu, rs, 1);
            rs += __shfl_xor_sync(0xffffffffu, rs, 2);
            l_run[r2] = l_run[r2] * corr[r2] + rs;
        }
        #pragma unroll
        for (int j = 0; j < 8; j++) {
            o[j][0] *= corr[0]; o[j][1] *= corr[0];
            o[j][2] *= corr[1]; o[j][3] *= corr[1];
        }

        #pragma unroll
        for (int kf = 0; kf < 4; kf++) {
            unsigned ph[4], pl[4];
            bfsplit2(s[2 * kf][0],     s[2 * kf][1],     ph[0], pl[0]);
            bfsplit2(s[2 * kf][2],     s[2 * kf][3],     ph[1], pl[1]);
            bfsplit2(s[2 * kf + 1][0], s[2 * kf + 1][1], ph[2], pl[2]);
            bfsplit2(s[2 * kf + 1][2], s[2 * kf + 1][3], ph[3], pl[3]);
            #pragma unroll
            for (int j = 0; j < 8; j++) {
                unsigned vh2[2], vl2[2];
                vh2[0] = Vh[(kf * 8 + tg) * LDV + j * 8 + g];
                vh2[1] = Vh[(kf * 8 + tg + 4) * LDV + j * 8 + g];
                vl2[0] = Vl[(kf * 8 + tg) * LDV + j * 8 + g];
                vl2[1] = Vl[(kf * 8 + tg + 4) * LDV + j * 8 + g];
                mma16(o[j], ph, vh2);
                mma16(o[j], ph, vl2);
                mma16(o[j], pl, vh2);
            }
        }
        __syncthreads();
    }

    float inv0 = 1.f / l_run[0], inv1 = 1.f / l_run[1];
    int row0 = b * Sc + qt * 128 + warp * 16 + g;
    #pragma unroll
    for (int j = 0; j < 8; j++) {
        int wcol = n * 32 + j * 4 + tg;      // (n*Dc + j*8 + 2tg)/2
        unsigned h0, l0, h1, l1;
        bfsplit2(o[j][0] * inv0, o[j][1] * inv0, h0, l0);
        bfsplit2(o[j][2] * inv1, o[j][3] * inv1, h1, l1);
        Ohi[(size_t)row0 * (Hc / 2) + wcol] = h0;
        Olo[(size_t)row0 * (Hc / 2) + wcol] = l0;
        Ohi[(size_t)(row0 + 8) * (Hc / 2) + wcol] = h1;
        Olo[(size_t)(row0 + 8) * (Hc / 2) + wcol] = l1;
    }
}

// ---------------------------------------------------------------------------
// LayerNorm over H=1024, fp32 out + optional split words
// ---------------------------------------------------------------------------
__device__ __forceinline__ float block_sum_256(float v) {
    __shared__ float sh[8];
    #pragma unroll
    for (int o = 16; o > 0; o >>= 1) v += __shfl_xor_sync(0xffffffffu, v, o);
    __syncthreads();
    if ((threadIdx.x & 31) == 0) sh[threadIdx.x >> 5] = v;
    __syncthreads();
    float t = sh[0];
    #pragma unroll
    for (int i = 1; i < 8; i++) t += sh[i];
    return t;
}

__global__ __launch_bounds__(256) void ln_kernel(
    const float* __restrict__ x, const float* __restrict__ ln,
    float* __restrict__ out, unsigned* __restrict__ ohi, unsigned* __restrict__ olo)
{
    const int row = blockIdx.x, tid = threadIdx.x;
    float4 v = ((const float4*)(x + (size_t)row * Hc))[tid];
    float s = v.x + v.y + v.z + v.w;
    s = block_sum_256(s);
    const float mean = s * (1.f / Hc);
    float dx = v.x - mean, dy = v.y - mean, dz = v.z - mean, dw = v.w - mean;
    float q = dx * dx + dy * dy + dz * dz + dw * dw;
    q = block_sum_256(q);
    const float inv = rsqrtf(q * (1.f / Hc) + LN_EPS);
    const int c = tid * 4;
    float4 gm = ((const float4*)ln)[tid];
    float4 bt = ((const float4*)(ln + Hc))[tid];
    float y0 = dx * inv * gm.x + bt.x;
    float y1 = dy * inv * gm.y + bt.y;
    float y2 = dz * inv * gm.z + bt.z;
    float y3 = dw * inv * gm.w + bt.w;
    ((float4*)(out + (size_t)row * Hc))[tid] = make_float4(y0, y1, y2, y3);
    if (ohi) {
        unsigned h0, l0, h1, l1;
        bfsplit2(y0, y1, h0, l0);
        bfsplit2(y2, y3, h1, l1);
        ((uint2*)(ohi + (size_t)row * (Hc / 2)))[tid] = make_uint2(h0, h1);
        ((uint2*)(olo + (size_t)row * (Hc / 2)))[tid] = make_uint2(l0, l1);
    }
    (void)c;
}

// ---------------------------------------------------------------------------
// Orchestration
// ---------------------------------------------------------------------------
extern "C" void kernel_launch(void* const* d_in, const int* in_sizes, int n_in,
                              void* d_out, int out_size)
{
    const float* hidden   = (const float*)d_in[0];
    const float* enc      = (const float*)d_in[1];
    const int*   amask    = (const int*)d_in[2];
    const int*   emask    = (const int*)d_in[3];
    const float* sa_qkv_w = (const float*)d_in[4];
    const float* sa_qkv_b = (const float*)d_in[5];
    const float* sa_out_w = (const float*)d_in[6];
    const float* sa_out_b = (const float*)d_in[7];
    const float* sa_ln    = (const float*)d_in[8];
    const float* ca_qkv_w = (const float*)d_in[9];
    const float* ca_qkv_b = (const float*)d_in[10];
    const float* ca_out_w = (const float*)d_in[11];
    const float* ca_out_b = (const float*)d_in[12];
    const float* ca_ln    = (const float*)d_in[13];
    const float* o1_w     = (const float*)d_in[14];
    const float* o1_b     = (const float*)d_in[15];
    const float* o1_ln    = (const float*)d_in[16];
    const float* ffn_w    = (const float*)d_in[17];
    const float* ffn_b    = (const float*)d_in[18];
    const float* o2_w     = (const float*)d_in[19];
    const float* o2_b     = (const float*)d_in[20];
    const float* o2_ln    = (const float*)d_in[21];
    float* out = (float*)d_out;

    cudaFuncSetAttribute(gemm_ps, cudaFuncAttributeMaxDynamicSharedMemorySize, G_SMEM);
    cudaFuncSetAttribute(attn_tc, cudaFuncAttributeMaxDynamicSharedMemorySize, ATTN_SMEM);

    float *h, *q, *k, *v, *t, *x2, *x3;
    unsigned *whi, *wlo;
    unsigned *hs_hi, *hs_lo, *es_hi, *es_lo, *as_hi, *as_lo;
    unsigned *x1_hi, *x1_lo, *x3_hi, *x3_lo, *in_hi, *in_lo;
    cudaGetSymbolAddress((void**)&h,  g_h);
    cudaGetSymbolAddress((void**)&q,  g_q);
    cudaGetSymbolAddress((void**)&k,  g_k);
    cudaGetSymbolAddress((void**)&v,  g_v);
    cudaGetSymbolAddress((void**)&t,  g_t);
    cudaGetSymbolAddress((void**)&x2, g_x2);
    cudaGetSymbolAddress((void**)&x3, g_x3);
    cudaGetSymbolAddress((void**)&whi, g_whi);
    cudaGetSymbolAddress((void**)&wlo, g_wlo);
    cudaGetSymbolAddress((void**)&hs_hi, g_hs_hi);
    cudaGetSymbolAddress((void**)&hs_lo, g_hs_lo);
    cudaGetSymbolAddress((void**)&es_hi, g_es_hi);
    cudaGetSymbolAddress((void**)&es_lo, g_es_lo);
    cudaGetSymbolAddress((void**)&as_hi, g_as_hi);
    cudaGetSymbolAddress((void**)&as_lo, g_as_lo);
    cudaGetSymbolAddress((void**)&x1_hi, g_x1_hi);
    cudaGetSymbolAddress((void**)&x1_lo, g_x1_lo);
    cudaGetSymbolAddress((void**)&x3_hi, g_x3_hi);
    cudaGetSymbolAddress((void**)&x3_lo, g_x3_lo);
    cudaGetSymbolAddress((void**)&in_hi, g_in_hi);
    cudaGetSymbolAddress((void**)&in_lo, g_in_lo);

    cudaMemcpyAsync(h, hidden, (size_t)Mrows * Hc * sizeof(float),
                    cudaMemcpyDeviceToDevice, 0);

    // ---- weight arena offsets (words) ----
    const size_t HH2 = (size_t)Hc * Hc / 2;        // 524288
    const size_t QKV2 = 3 * HH2;                   // 1572864
    const size_t FF2 = (size_t)Hc * Fc / 2;        // 2097152
    const size_t PL = 2 * QKV2 + 3 * HH2 + 2 * FF2;  // per-layer words

    // ---- pre-split weights + initial activations ----
    for (int i = 0; i < LAYERS; i++) {
        size_t o = (size_t)i * PL;
        split_w<<<(int)((QKV2 + 255) / 256), 256>>>(sa_qkv_w + (size_t)i * 3 * Hc * Hc,
                                                    whi + o, wlo + o, 3 * Hc / 2, Hc);
        split_w<<<(int)((HH2 + 255) / 256), 256>>>(sa_out_w + (size_t)i * Hc * Hc,
                                                   whi + o + QKV2, wlo + o + QKV2, Hc / 2, Hc);
        split_w<<<(int)((QKV2 + 255) / 256), 256>>>(ca_qkv_w + (size_t)i * 3 * Hc * Hc,
                                                    whi + o + QKV2 + HH2, wlo + o + QKV2 + HH2,
                                                    3 * Hc / 2, Hc);
        split_w<<<(int)((HH2 + 255) / 256), 256>>>(ca_out_w + (size_t)i * Hc * Hc,
                                                   whi + o + 2 * QKV2 + HH2, wlo + o + 2 * QKV2 + HH2,
                                                   Hc / 2, Hc);
        split_w<<<(int)((HH2 + 255) / 256), 256>>>(o1_w + (size_t)i * Hc * Hc,
                                                   whi + o + 2 * QKV2 + 2 * HH2,
                                                   wlo + o + 2 * QKV2 + 2 * HH2, Hc / 2, Hc);
        split_w<<<(int)((FF2 + 255) / 256), 256>>>(ffn_w + (size_t)i * Hc * Fc,
                                                   whi + o + 2 * QKV2 + 3 * HH2,
                                                   wlo + o + 2 * QKV2 + 3 * HH2, Hc / 2, Fc);
        split_w<<<(int)((FF2 + 255) / 256), 256>>>(o2_w + (size_t)i * Fc * Hc,
                                                   whi + o + 2 * QKV2 + 3 * HH2 + FF2,
                                                   wlo + o + 2 * QKV2 + 3 * HH2 + FF2, Fc / 2, Hc);
    }
    const int ACTW = Mrows * Hc / 2;
    split_act<<<(ACTW + 255) / 256, 256>>>((const float2*)hidden, hs_hi, hs_lo, ACTW);
    split_act<<<(ACTW + 255) / 256, 256>>>((const float2*)enc, es_hi, es_lo, ACTW);

    const dim3 g1(Hc / 128, Mrows / 128);
    const dim3 gF(Fc / 128, Mrows / 128);
    const int attnBlocks = Bc * NHc * (Sc / 128);

    for (int i = 0; i < LAYERS; i++) {
        size_t o = (size_t)i * PL;
        // ---- self attention ----
        gemm_ps<<<g1, 256, G_SMEM>>>(hs_hi, hs_lo, whi + o, wlo + o,
                                     sa_qkv_b + (size_t)i * 3 * Hc, nullptr,
                                     q, nullptr, nullptr, Mrows, Hc, Hc, 0);
        gemm_ps<<<g1, 256, G_SMEM>>>(hs_hi, hs_lo, whi + o + HH2, wlo + o + HH2,
                                     sa_qkv_b + (size_t)i * 3 * Hc + Hc, nullptr,
                                     k, nullptr, nullptr, Mrows, Hc, Hc, 0);
        gemm_ps<<<g1, 256, G_SMEM>>>(hs_hi, hs_lo, whi + o + 2 * HH2, wlo + o + 2 * HH2,
                                     sa_qkv_b + (size_t)i * 3 * Hc + 2 * Hc, nullptr,
                                     v, nullptr, nullptr, Mrows, Hc, Hc, 0);
        attn_tc<<<attnBlocks, 256, ATTN_SMEM>>>(q, k, v, amask, as_hi, as_lo);
        gemm_ps<<<g1, 256, G_SMEM>>>(as_hi, as_lo, whi + o + QKV2, wlo + o + QKV2,
                                     sa_out_b + (size_t)i * Hc, h,
                                     t, nullptr, nullptr, Mrows, Hc, Hc, 0);
        ln_kernel<<<Mrows, 256>>>(t, sa_ln + (size_t)i * 2 * Hc, t, x1_hi, x1_lo);

        // ---- cross attention ----
        size_t oc = o + QKV2 + HH2;
        gemm_ps<<<g1, 256, G_SMEM>>>(hs_hi, hs_lo, whi + oc, wlo + oc,
                                     ca_qkv_b + (size_t)i * 3 * Hc, nullptr,
                                     q, nullptr, nullptr, Mrows, Hc, Hc, 0);
        gemm_ps<<<g1, 256, G_SMEM>>>(es_hi, es_lo, whi + oc + HH2, wlo + oc + HH2,
                                     ca_qkv_b + (size_t)i * 3 * Hc + Hc, nullptr,
                                     k, nullptr, nullptr, Mrows, Hc, Hc, 0);
        gemm_ps<<<g1, 256, G_SMEM>>>(es_hi, es_lo, whi + oc + 2 * HH2, wlo + oc + 2 * HH2,
                                     ca_qkv_b + (size_t)i * 3 * Hc + 2 * Hc, nullptr,
                                     v, nullptr, nullptr, Mrows, Hc, Hc, 0);
        attn_tc<<<attnBlocks, 256, ATTN_SMEM>>>(q, k, v, emask, as_hi, as_lo);
        gemm_ps<<<g1, 256, G_SMEM>>>(as_hi, as_lo, whi + o + 2 * QKV2 + HH2,
                                     wlo + o + 2 * QKV2 + HH2,
                                     ca_out_b + (size_t)i * Hc, h,
                                     v, nullptr, nullptr, Mrows, Hc, Hc, 0);
        ln_kernel<<<Mrows, 256>>>(v, ca_ln + (size_t)i * 2 * Hc, x2, nullptr, nullptr);

        // ---- output_1 ----
        gemm_ps<<<g1, 256, G_SMEM>>>(x1_hi, x1_lo, whi + o + 2 * QKV2 + 2 * HH2,
                                     wlo + o + 2 * QKV2 + 2 * HH2,
                                     o1_b + (size_t)i * Hc, x2,
                                     t, nullptr, nullptr, Mrows, Hc, Hc, 0);
        ln_kernel<<<Mrows, 256>>>(t, o1_ln + (size_t)i * 2 * Hc, x3, x3_hi, x3_lo);

        // ---- FFN ----
        gemm_ps<<<gF, 256, G_SMEM>>>(x3_hi, x3_lo, whi + o + 2 * QKV2 + 3 * HH2,
                                     wlo + o + 2 * QKV2 + 3 * HH2,
                                     ffn_b + (size_t)i * Fc, nullptr,
                                     nullptr, in_hi, in_lo, Mrows, Fc, Hc, 1);
        gemm_ps<<<g1, 256, G_SMEM>>>(in_hi, in_lo, whi + o + 2 * QKV2 + 3 * HH2 + FF2,
                                     wlo + o + 2 * QKV2 + 3 * HH2 + FF2,
                                     o2_b + (size_t)i * Hc, x3,
                                     t, nullptr, nullptr, Mrows, Hc, Fc, 0);
        if (i == LAYERS - 1)
            ln_kernel<<<Mrows, 256>>>(t, o2_ln + (size_t)i * 2 * Hc, out, nullptr, nullptr);
        else
            ln_kernel<<<Mrows, 256>>>(t, o2_ln + (size_t)i * 2 * Hc, h, hs_hi, hs_lo);
    }
}

// round 15
// speedup vs baseline: 1.7855x; 1.1386x over previous
#include <cuda_runtime.h>
#include <cuda_bf16.h>
#include <math.h>
#include <stdint.h>

#define LAYERS 6
#define Hc 1024
#define NHc 16
#define Dc 64
#define Fc 4096
#define Bc 4
#define Sc 512
#define Mrows (Bc * Sc)
#define LN_EPS 1e-12f
#define GELU_C 0.7978845608028654f

// fp32 scratch
__device__ float g_h[Mrows * Hc];
__device__ float g_q[Mrows * Hc];
__device__ float g_k[Mrows * Hc];
__device__ float g_v[Mrows * Hc];
__device__ float g_x2[Mrows * Hc];
__device__ float g_x3[Mrows * Hc];
__device__ float g_part[4 * Mrows * Hc];   // split-K partials (Z<=4)

// pre-split weight arenas (hi/lo bf16x2 words, pairs along K)
#define WARENA (53477376ULL)
__device__ unsigned g_whi[WARENA];
__device__ unsigned g_wlo[WARENA];

// pre-split activation word buffers [M][K/2]
__device__ unsigned g_hs_hi[Mrows * Hc / 2],  g_hs_lo[Mrows * Hc / 2];
__device__ unsigned g_es_hi[Mrows * Hc / 2],  g_es_lo[Mrows * Hc / 2];
__device__ unsigned g_as_hi[Mrows * Hc / 2],  g_as_lo[Mrows * Hc / 2];
__device__ unsigned g_x1_hi[Mrows * Hc / 2],  g_x1_lo[Mrows * Hc / 2];
__device__ unsigned g_x3_hi[Mrows * Hc / 2],  g_x3_lo[Mrows * Hc / 2];
__device__ unsigned g_in_hi[Mrows * Fc / 2],  g_in_lo[Mrows * Fc / 2];

// ---------------------------------------------------------------------------
// Helpers
// ---------------------------------------------------------------------------
__device__ __forceinline__ uint32_t smem_u32(const void* p) {
    uint32_t a;
    asm("{ .reg .u64 t; cvta.to.shared.u64 t, %1; cvt.u32.u64 %0, t; }" : "=r"(a) : "l"(p));
    return a;
}
__device__ __forceinline__ void bfsplit2(float x0, float x1, unsigned& hi, unsigned& lo) {
    unsigned h;
    asm("cvt.rn.bf16x2.f32 %0, %1, %2;" : "=r"(h) : "f"(x1), "f"(x0));
    float h0 = __uint_as_float(h << 16);
    float h1 = __uint_as_float(h & 0xffff0000u);
    unsigned l;
    asm("cvt.rn.bf16x2.f32 %0, %1, %2;" : "=r"(l) : "f"(x1 - h1), "f"(x0 - h0));
    hi = h; lo = l;
}
__device__ __forceinline__ void mma16(float* c, const unsigned* a, const unsigned* b) {
    asm("mma.sync.aligned.m16n8k16.row.col.f32.bf16.bf16.f32 "
        "{%0,%1,%2,%3}, {%4,%5,%6,%7}, {%8,%9}, {%0,%1,%2,%3};"
        : "+f"(c[0]), "+f"(c[1]), "+f"(c[2]), "+f"(c[3])
        : "r"(a[0]), "r"(a[1]), "r"(a[2]), "r"(a[3]), "r"(b[0]), "r"(b[1]));
}
__device__ __forceinline__ void cp16(uint32_t dst, const void* src) {
    asm volatile("cp.async.cg.shared.global [%0], [%1], 16;" :: "r"(dst), "l"(src));
}
__device__ __forceinline__ float gelu_new(float x) {
    float z = GELU_C * (x + 0.044715f * x * x * x);
    float e = __expf(2.f * z);
    float th = (e - 1.f) / (e + 1.f);
    return 0.5f * x * (1.0f + th);
}

// ---------------------------------------------------------------------------
// Split kernels (batched across layers at call sites)
// ---------------------------------------------------------------------------
__global__ __launch_bounds__(256) void split_w(
    const float* __restrict__ src, unsigned* __restrict__ hi,
    unsigned* __restrict__ lo, int K2, int N)
{
    int idx = blockIdx.x * 256 + threadIdx.x;
    if (idx >= K2 * N) return;
    int k2 = idx / N, n = idx - k2 * N;
    float f0 = src[(size_t)(2 * k2) * N + n];
    float f1 = src[(size_t)(2 * k2 + 1) * N + n];
    unsigned h, l;
    bfsplit2(f0, f1, h, l);
    hi[idx] = h; lo[idx] = l;
}
__global__ __launch_bounds__(256) void split_act(
    const float2* __restrict__ src, unsigned* __restrict__ hi,
    unsigned* __restrict__ lo, int total)
{
    int idx = blockIdx.x * 256 + threadIdx.x;
    if (idx >= total) return;
    float2 f = src[idx];
    unsigned h, l;
    bfsplit2(f.x, f.y, h, l);
    hi[idx] = h; lo[idx] = l;
}

// ---------------------------------------------------------------------------
// Shared GEMM core: CTA 128x128, 16-k steps, 3-stage cp.async pipeline,
// 8 warps (2x4), warp tile 64x32. Stage layout (words):
// Ahi[128][12] @0 | Alo @1536 | Bhi[8][136] @3072 | Blo @4160; stage 5248 w.
// ---------------------------------------------------------------------------
#define STG_W 5248
#define STG_B 20992
#define G_SMEM (3 * STG_B)

__device__ __forceinline__ void gemm_core(
    const unsigned* __restrict__ Ahi, const unsigned* __restrict__ Alo,
    const unsigned* __restrict__ Whi, const unsigned* __restrict__ Wlo,
    int K2, int N, int kw0, int T, int bm, int bn,
    char* smem, float acc[4][4][4])
{
    unsigned* sw = (unsigned*)smem;
    const uint32_t sb = smem_u32(smem);
    const int tid = threadIdx.x, lane = tid & 31, warp = tid >> 5;
    const int wr = warp >> 2, wc = warp & 3;
    const int g = lane >> 2, tg = lane & 3;
    const int arow = tid >> 1, ahalf = tid & 1;
    const int br_ = tid >> 5, bc_ = tid & 31;

    auto issue = [&](int t) {
        const uint32_t st = sb + (uint32_t)(t % 3) * STG_B;
        const size_t ao = (size_t)(bm + arow) * K2 + kw0 + t * 8 + ahalf * 4;
        cp16(st + arow * 48 + ahalf * 16, Ahi + ao);
        cp16(st + 6144 + arow * 48 + ahalf * 16, Alo + ao);
        const size_t wo = (size_t)(kw0 + t * 8 + br_) * N + bn + bc_ * 4;
        cp16(st + 12288 + br_ * 544 + bc_ * 16, Whi + wo);
        cp16(st + 16640 + br_ * 544 + bc_ * 16, Wlo + wo);
        asm volatile("cp.async.commit_group;" ::: "memory");
    };
    auto compute = [&](int t) {
        const unsigned* S = sw + (size_t)(t % 3) * STG_W;
        unsigned ah[4][4], al_[4][4];
        #pragma unroll
        for (int i = 0; i < 4; i++) {
            const int rb = wr * 64 + i * 16 + g;
            ah[i][0]  = S[rb * 12 + tg];        ah[i][1]  = S[(rb + 8) * 12 + tg];
            ah[i][2]  = S[rb * 12 + tg + 4];    ah[i][3]  = S[(rb + 8) * 12 + tg + 4];
            al_[i][0] = S[1536 + rb * 12 + tg];      al_[i][1] = S[1536 + (rb + 8) * 12 + tg];
            al_[i][2] = S[1536 + rb * 12 + tg + 4];  al_[i][3] = S[1536 + (rb + 8) * 12 + tg + 4];
        }
        #pragma unroll
        for (int j = 0; j < 4; j++) {
            const int cb = wc * 32 + j * 8 + g;
            unsigned bh2[2], bl2[2];
            bh2[0] = S[3072 + tg * 136 + cb];       bh2[1] = S[3072 + (tg + 4) * 136 + cb];
            bl2[0] = S[4160 + tg * 136 + cb];       bl2[1] = S[4160 + (tg + 4) * 136 + cb];
            #pragma unroll
            for (int i = 0; i < 4; i++) {
                mma16(acc[i][j], ah[i],  bh2);
                mma16(acc[i][j], ah[i],  bl2);
                mma16(acc[i][j], al_[i], bh2);
            }
        }
    };

    issue(0);
    if (T > 1) issue(1);
    for (int t = 0; t < T; t++) {
        asm volatile("cp.async.wait_group 1;" ::: "memory");
        __syncthreads();
        compute(t);
        if (t + 2 < T) issue(t + 2);
        else asm volatile("cp.async.commit_group;" ::: "memory");
        __syncthreads();
    }
}

// ---- fused QKV: z selects weight (z*HH2W), bias (z*Hc), output, and A ----
#define HH2W (Hc * Hc / 2)
__global__ __launch_bounds__(256, 2) void gemm_qkv(
    const unsigned* __restrict__ A0hi, const unsigned* __restrict__ A0lo,
    const unsigned* __restrict__ A1hi, const unsigned* __restrict__ A1lo,
    const unsigned* __restrict__ Whi, const unsigned* __restrict__ Wlo,
    const float* __restrict__ bias,
    float* __restrict__ Oq, float* __restrict__ Ok, float* __restrict__ Ov)
{
    extern __shared__ char smem[];
    const int z = blockIdx.z;
    const unsigned* Ahi = (z == 0) ? A0hi : A1hi;
    const unsigned* Alo = (z == 0) ? A0lo : A1lo;
    const int bm = blockIdx.y * 128, bn = blockIdx.x * 128;

    float acc[4][4][4];
    #pragma unroll
    for (int i = 0; i < 4; i++)
        #pragma unroll
        for (int j = 0; j < 4; j++)
            #pragma unroll
            for (int r = 0; r < 4; r++) acc[i][j][r] = 0.f;

    gemm_core(Ahi, Alo, Whi + (size_t)z * HH2W, Wlo + (size_t)z * HH2W,
              Hc / 2, Hc, 0, Hc / 16, bm, bn, smem, acc);

    float* C = (z == 0) ? Oq : (z == 1) ? Ok : Ov;
    const float* bz = bias + z * Hc;
    const int lane = threadIdx.x & 31, warp = threadIdx.x >> 5;
    const int wr = warp >> 2, wc = warp & 3, g = lane >> 2, tg = lane & 3;
    #pragma unroll
    for (int i = 0; i < 4; i++) {
        int row0 = bm + wr * 64 + i * 16 + g;
        #pragma unroll
        for (int j = 0; j < 4; j++) {
            int col = bn + wc * 32 + j * 8 + 2 * tg;
            float2 b2 = *(const float2*)(bz + col);
            *(float2*)(C + (size_t)row0 * Hc + col) =
                make_float2(acc[i][j][0] + b2.x, acc[i][j][1] + b2.y);
            *(float2*)(C + (size_t)(row0 + 8) * Hc + col) =
                make_float2(acc[i][j][2] + b2.x, acc[i][j][3] + b2.y);
        }
    }
}

// ---- direct GEMM with epilogue (used for FFN-up) ----
__global__ __launch_bounds__(256, 2) void gemm_ps(
    const unsigned* __restrict__ Ahi, const unsigned* __restrict__ Alo,
    const unsigned* __restrict__ Whi, const unsigned* __restrict__ Wlo,
    const float* __restrict__ bias,
    unsigned* __restrict__ Chi, unsigned* __restrict__ Clo,
    int N, int K, int fuse_gelu)
{
    extern __shared__ char smem[];
    const int bm = blockIdx.y * 128, bn = blockIdx.x * 128;
    float acc[4][4][4];
    #pragma unroll
    for (int i = 0; i < 4; i++)
        #pragma unroll
        for (int j = 0; j < 4; j++)
            #pragma unroll
            for (int r = 0; r < 4; r++) acc[i][j][r] = 0.f;

    gemm_core(Ahi, Alo, Whi, Wlo, K / 2, N, 0, K / 16, bm, bn, smem, acc);

    const int lane = threadIdx.x & 31, warp = threadIdx.x >> 5;
    const int wr = warp >> 2, wc = warp & 3, g = lane >> 2, tg = lane & 3;
    #pragma unroll
    for (int i = 0; i < 4; i++) {
        int row0 = bm + wr * 64 + i * 16 + g;
        #pragma unroll
        for (int j = 0; j < 4; j++) {
            int col = bn + wc * 32 + j * 8 + 2 * tg;
            float2 b2 = *(const float2*)(bias + col);
            float v0 = acc[i][j][0] + b2.x, v1 = acc[i][j][1] + b2.y;
            float v2 = acc[i][j][2] + b2.x, v3 = acc[i][j][3] + b2.y;
            if (fuse_gelu) {
                v0 = gelu_new(v0); v1 = gelu_new(v1);
                v2 = gelu_new(v2); v3 = gelu_new(v3);
            }
            unsigned h0, l0, h1, l1;
            bfsplit2(v0, v1, h0, l0);
            bfsplit2(v2, v3, h1, l1);
            size_t w0 = (size_t)row0 * (N >> 1) + (col >> 1);
            size_t w1 = (size_t)(row0 + 8) * (N >> 1) + (col >> 1);
            Chi[w0] = h0; Clo[w0] = l0;
            Chi[w1] = h1; Clo[w1] = l1;
        }
    }
}

// ---- split-K GEMM: z-th K-slice -> fp32 partial (no bias) ----
__global__ __launch_bounds__(256, 2) void gemm_pk(
    const unsigned* __restrict__ Ahi, const unsigned* __restrict__ Alo,
    const unsigned* __restrict__ Whi, const unsigned* __restrict__ Wlo,
    float* __restrict__ P, int K)
{
    extern __shared__ char smem[];
    const int z = blockIdx.z, Z = gridDim.z;
    const int Ks = K / Z;
    const int bm = blockIdx.y * 128, bn = blockIdx.x * 128;
    float acc[4][4][4];
    #pragma unroll
    for (int i = 0; i < 4; i++)
        #pragma unroll
        for (int j = 0; j < 4; j++)
            #pragma unroll
            for (int r = 0; r < 4; r++) acc[i][j][r] = 0.f;

    gemm_core(Ahi, Alo, Whi, Wlo, K / 2, Hc, z * (Ks / 2), Ks / 16, bm, bn, smem, acc);

    float* Pz = P + (size_t)z * Mrows * Hc;
    const int lane = threadIdx.x & 31, warp = threadIdx.x >> 5;
    const int wr = warp >> 2, wc = warp & 3, g = lane >> 2, tg = lane & 3;
    #pragma unroll
    for (int i = 0; i < 4; i++) {
        int row0 = bm + wr * 64 + i * 16 + g;
        #pragma unroll
        for (int j = 0; j < 4; j++) {
            int col = bn + wc * 32 + j * 8 + 2 * tg;
            *(float2*)(Pz + (size_t)row0 * Hc + col) = make_float2(acc[i][j][0], acc[i][j][1]);
            *(float2*)(Pz + (size_t)(row0 + 8) * Hc + col) = make_float2(acc[i][j][2], acc[i][j][3]);
        }
    }
}

// ---------------------------------------------------------------------------
// Fused partial-sum + bias + residual + LayerNorm (+ optional fp32/split out)
// ---------------------------------------------------------------------------
__device__ __forceinline__ float block_sum_256(float v) {
    __shared__ float sh[8];
    #pragma unroll
    for (int o = 16; o > 0; o >>= 1) v += __shfl_xor_sync(0xffffffffu, v, o);
    __syncthreads();
    if ((threadIdx.x & 31) == 0) sh[threadIdx.x >> 5] = v;
    __syncthreads();
    float t = sh[0];
    #pragma unroll
    for (int i = 1; i < 8; i++) t += sh[i];
    return t;
}

__global__ __launch_bounds__(256) void ln_red(
    const float* __restrict__ P, int Z,
    const float* __restrict__ bias, const float* __restrict__ add,
    const float* __restrict__ lnw,
    float* __restrict__ outF, unsigned* __restrict__ ohi, unsigned* __restrict__ olo)
{
    const int row = blockIdx.x, tid = threadIdx.x;
    const size_t MN = (size_t)Mrows * Hc;
    float4 v = ((const float4*)(P + (size_t)row * Hc))[tid];
    for (int z = 1; z < Z; z++) {
        float4 p = ((const float4*)(P + z * MN + (size_t)row * Hc))[tid];
        v.x += p.x; v.y += p.y; v.z += p.z; v.w += p.w;
    }
    float4 b4 = ((const float4*)bias)[tid];
    float4 a4 = ((const float4*)(add + (size_t)row * Hc))[tid];
    v.x += b4.x + a4.x; v.y += b4.y + a4.y; v.z += b4.z + a4.z; v.w += b4.w + a4.w;

    float s = v.x + v.y + v.z + v.w;
    s = block_sum_256(s);
    const float mean = s * (1.f / Hc);
    float dx = v.x - mean, dy = v.y - mean, dz = v.z - mean, dw = v.w - mean;
    float q = dx * dx + dy * dy + dz * dz + dw * dw;
    q = block_sum_256(q);
    const float inv = rsqrtf(q * (1.f / Hc) + LN_EPS);
    float4 gm = ((const float4*)lnw)[tid];
    float4 bt = ((const float4*)(lnw + Hc))[tid];
    float y0 = dx * inv * gm.x + bt.x;
    float y1 = dy * inv * gm.y + bt.y;
    float y2 = dz * inv * gm.z + bt.z;
    float y3 = dw * inv * gm.w + bt.w;
    if (outF)
        ((float4*)(outF + (size_t)row * Hc))[tid] = make_float4(y0, y1, y2, y3);
    if (ohi) {
        unsigned h0, l0, h1, l1;
        bfsplit2(y0, y1, h0, l0);
        bfsplit2(y2, y3, h1, l1);
        ((uint2*)(ohi + (size_t)row * (Hc / 2)))[tid] = make_uint2(h0, h1);
        ((uint2*)(olo + (size_t)row * (Hc / 2)))[tid] = make_uint2(l0, l1);
    }
}

// ---------------------------------------------------------------------------
// FlashAttention (bf16x2 split, m16n8k16) — unchanged core; split-word output.
// ---------------------------------------------------------------------------
#define LDQ 36
#define LDK 72
#define LDV 72
#define ATTN_SMEM ((2 * 128 * LDQ + 2 * 32 * LDK + 2 * 32 * LDV) * 4 + Sc * 4)

__global__ __launch_bounds__(256) void attn_tc(
    const float* __restrict__ Q, const float* __restrict__ Kin,
    const float* __restrict__ Vin, const int* __restrict__ mask,
    unsigned* __restrict__ Ohi, unsigned* __restrict__ Olo)
{
    extern __shared__ unsigned sm_a[];
    unsigned* Qh = sm_a;
    unsigned* Ql = Qh + 128 * LDQ;
    unsigned* Kh = Ql + 128 * LDQ;
    unsigned* Kl = Kh + 32 * LDK;
    unsigned* Vh = Kl + 32 * LDK;
    unsigned* Vl = Vh + 32 * LDV;
    float* madd = (float*)(Vl + 32 * LDV);

    const int tid = threadIdx.x, lane = tid & 31, warp = tid >> 5;
    const int g = lane >> 2, tg = lane & 3;
    const int qt = blockIdx.x & 3;
    const int n  = (blockIdx.x >> 2) & 15;
    const int b  = blockIdx.x >> 6;

    for (int j = tid; j < Sc; j += 256)
        madd[j] = mask[b * Sc + j] ? 0.f : -10000.f;

    {
        int r = tid >> 1, d0 = (tid & 1) * 32;
        const float* qp = Q + (size_t)(b * Sc + qt * 128 + r) * Hc + n * Dc + d0;
        #pragma unroll
        for (int i = 0; i < 32; i += 8) {
            float4 u = *(const float4*)(qp + i);
            float4 w = *(const float4*)(qp + i + 4);
            unsigned h0, l0, h1, l1, h2, l2, h3, l3;
            bfsplit2(u.x, u.y, h0, l0); bfsplit2(u.z, u.w, h1, l1);
            bfsplit2(w.x, w.y, h2, l2); bfsplit2(w.z, w.w, h3, l3);
            *(uint4*)&Qh[r * LDQ + ((d0 + i) >> 1)] = make_uint4(h0, h1, h2, h3);
            *(uint4*)&Ql[r * LDQ + ((d0 + i) >> 1)] = make_uint4(l0, l1, l2, l3);
        }
    }
    __syncthreads();

    float o[8][4];
    #pragma unroll
    for (int j = 0; j < 8; j++)
        #pragma unroll
        for (int r = 0; r < 4; r++) o[j][r] = 0.f;
    float m_run[2] = {-1e30f, -1e30f};
    float l_run[2] = {0.f, 0.f};

    for (int kv = 0; kv < Sc; kv += 64) {
        {
            int r = tid >> 2, d0 = (tid & 3) * 16;
            const float* kpp = Kin + (size_t)(b * Sc + kv + r) * Hc + n * Dc + d0;
            float4 u = *(const float4*)(kpp);
            float4 w = *(const float4*)(kpp + 4);
            float4 x = *(const float4*)(kpp + 8);
            float4 y = *(const float4*)(kpp + 12);
            float pv[16] = {u.x, u.y, u.z, u.w, w.x, w.y, w.z, w.w,
                            x.x, x.y, x.z, x.w, y.x, y.y, y.z, y.w};
            #pragma unroll
            for (int p = 0; p < 8; p++) {
                unsigned h, l;
                bfsplit2(pv[2 * p], pv[2 * p + 1], h, l);
                Kh[((d0 >> 1) + p) * LDK + r] = h;
                Kl[((d0 >> 1) + p) * LDK + r] = l;
            }
            int kp2 = tid >> 3, dv0 = (tid & 7) * 8;
            const float* v0p = Vin + (size_t)(b * Sc + kv + 2 * kp2) * Hc + n * Dc + dv0;
            float4 a0 = *(const float4*)(v0p);
            float4 a1 = *(const float4*)(v0p + 4);
            float4 b0 = *(const float4*)(v0p + Hc);
            float4 b1 = *(const float4*)(v0p + Hc + 4);
            unsigned hh[8], ll[8];
            bfsplit2(a0.x, b0.x, hh[0], ll[0]); bfsplit2(a0.y, b0.y, hh[1], ll[1]);
            bfsplit2(a0.z, b0.z, hh[2], ll[2]); bfsplit2(a0.w, b0.w, hh[3], ll[3]);
            bfsplit2(a1.x, b1.x, hh[4], ll[4]); bfsplit2(a1.y, b1.y, hh[5], ll[5]);
            bfsplit2(a1.z, b1.z, hh[6], ll[6]); bfsplit2(a1.w, b1.w, hh[7], ll[7]);
            *(uint4*)&Vh[kp2 * LDV + dv0]     = make_uint4(hh[0], hh[1], hh[2], hh[3]);
            *(uint4*)&Vh[kp2 * LDV + dv0 + 4] = make_uint4(hh[4], hh[5], hh[6], hh[7]);
            *(uint4*)&Vl[kp2 * LDV + dv0]     = make_uint4(ll[0], ll[1], ll[2], ll[3]);
            *(uint4*)&Vl[kp2 * LDV + dv0 + 4] = make_uint4(ll[4], ll[5], ll[6], ll[7]);
        }
        __syncthreads();

        float s[8][4];
        #pragma unroll
        for (int j = 0; j < 8; j++)
            #pragma unroll
            for (int r = 0; r < 4; r++) s[j][r] = 0.f;
        #pragma unroll
        for (int kk2 = 0; kk2 < 32; kk2 += 8) {
            int rb = warp * 16 + g;
            unsigned qh[4], ql_[4];
            qh[0] = Qh[rb * LDQ + kk2 + tg];        qh[1] = Qh[(rb + 8) * LDQ + kk2 + tg];
            qh[2] = Qh[rb * LDQ + kk2 + tg + 4];    qh[3] = Qh[(rb + 8) * LDQ + kk2 + tg + 4];
            ql_[0] = Ql[rb * LDQ + kk2 + tg];       ql_[1] = Ql[(rb + 8) * LDQ + kk2 + tg];
            ql_[2] = Ql[rb * LDQ + kk2 + tg + 4];   ql_[3] = Ql[(rb + 8) * LDQ + kk2 + tg + 4];
            #pragma unroll
            for (int j = 0; j < 8; j++) {
                unsigned kh2[2], kl2[2];
                kh2[0] = Kh[(kk2 + tg) * LDK + j * 8 + g];
                kh2[1] = Kh[(kk2 + tg + 4) * LDK + j * 8 + g];
                kl2[0] = Kl[(kk2 + tg) * LDK + j * 8 + g];
                kl2[1] = Kl[(kk2 + tg + 4) * LDK + j * 8 + g];
                mma16(s[j], qh, kh2);
                mma16(s[j], qh, kl2);
                mma16(s[j], ql_, kh2);
            }
        }

        float corr[2];
        #pragma unroll
        for (int r2 = 0; r2 < 2; r2++) {
            float mx = m_run[r2];
            #pragma unroll
            for (int j = 0; j < 8; j++)
                #pragma unroll
                for (int c = 0; c < 2; c++) {
                    float val = s[j][r2 * 2 + c] * 0.125f + madd[kv + j * 8 + 2 * tg + c];
                    s[j][r2 * 2 + c] = val;
                    mx = fmaxf(mx, val);
                }
            mx = fmaxf(mx, __shfl_xor_sync(0xffffffffu, mx, 1));
            mx = fmaxf(mx, __shfl_xor_sync(0xffffffffu, mx, 2));
            corr[r2] = __expf(m_run[r2] - mx);
            m_run[r2] = mx;
            float rs = 0.f;
            #pragma unroll
            for (int j = 0; j < 8; j++)
                #pragma unroll
                for (int c = 0; c < 2; c++) {
                    float e = __expf(s[j][r2 * 2 + c] - mx);
                    s[j][r2 * 2 + c] = e;
                    rs += e;
                }
            rs += __shfl_xor_sync(0xffffffffu, rs, 1);
            rs += __shfl_xor_sync(0xffffffffu, rs, 2);
            l_run[r2] = l_run[r2] * corr[r2] + rs;
        }
        #pragma unroll
        for (int j = 0; j < 8; j++) {
            o[j][0] *= corr[0]; o[j][1] *= corr[0];
            o[j][2] *= corr[1]; o[j][3] *= corr[1];
        }

        #pragma unroll
        for (int kf = 0; kf < 4; kf++) {
            unsigned ph[4], pl[4];
            bfsplit2(s[2 * kf][0],     s[2 * kf][1],     ph[0], pl[0]);
            bfsplit2(s[2 * kf][2],     s[2 * kf][3],     ph[1], pl[1]);
            bfsplit2(s[2 * kf + 1][0], s[2 * kf + 1][1], ph[2], pl[2]);
            bfsplit2(s[2 * kf + 1][2], s[2 * kf + 1][3], ph[3], pl[3]);
            #pragma unroll
            for (int j = 0; j < 8; j++) {
                unsigned vh2[2], vl2[2];
                vh2[0] = Vh[(kf * 8 + tg) * LDV + j * 8 + g];
                vh2[1] = Vh[(kf * 8 + tg + 4) * LDV + j * 8 + g];
                vl2[0] = Vl[(kf * 8 + tg) * LDV + j * 8 + g];
                vl2[1] = Vl[(kf * 8 + tg + 4) * LDV + j * 8 + g];
                mma16(o[j], ph, vh2);
                mma16(o[j], ph, vl2);
                mma16(o[j], pl, vh2);
            }
        }
        __syncthreads();
    }

    float inv0 = 1.f / l_run[0], inv1 = 1.f / l_run[1];
    int row0 = b * Sc + qt * 128 + warp * 16 + g;
    #pragma unroll
    for (int j = 0; j < 8; j++) {
        int wcol = n * 32 + j * 4 + tg;
        unsigned h0, l0, h1, l1;
        bfsplit2(o[j][0] * inv0, o[j][1] * inv0, h0, l0);
        bfsplit2(o[j][2] * inv1, o[j][3] * inv1, h1, l1);
        Ohi[(size_t)row0 * (Hc / 2) + wcol] = h0;
        Olo[(size_t)row0 * (Hc / 2) + wcol] = l0;
        Ohi[(size_t)(row0 + 8) * (Hc / 2) + wcol] = h1;
        Olo[(size_t)(row0 + 8) * (Hc / 2) + wcol] = l1;
    }
}

// ---------------------------------------------------------------------------
// Orchestration
// ---------------------------------------------------------------------------
extern "C" void kernel_launch(void* const* d_in, const int* in_sizes, int n_in,
                              void* d_out, int out_size)
{
    const float* hidden   = (const float*)d_in[0];
    const float* enc      = (const float*)d_in[1];
    const int*   amask    = (const int*)d_in[2];
    const int*   emask    = (const int*)d_in[3];
    const float* sa_qkv_w = (const float*)d_in[4];
    const float* sa_qkv_b = (const float*)d_in[5];
    const float* sa_out_w = (const float*)d_in[6];
    const float* sa_out_b = (const float*)d_in[7];
    const float* sa_ln    = (const float*)d_in[8];
    const float* ca_qkv_w = (const float*)d_in[9];
    const float* ca_qkv_b = (const float*)d_in[10];
    const float* ca_out_w = (const float*)d_in[11];
    const float* ca_out_b = (const float*)d_in[12];
    const float* ca_ln    = (const float*)d_in[13];
    const float* o1_w     = (const float*)d_in[14];
    const float* o1_b     = (const float*)d_in[15];
    const float* o1_ln    = (const float*)d_in[16];
    const float* ffn_w    = (const float*)d_in[17];
    const float* ffn_b    = (const float*)d_in[18];
    const float* o2_w     = (const float*)d_in[19];
    const float* o2_b     = (const float*)d_in[20];
    const float* o2_ln    = (const float*)d_in[21];
    float* out = (float*)d_out;

    cudaFuncSetAttribute(gemm_qkv, cudaFuncAttributeMaxDynamicSharedMemorySize, G_SMEM);
    cudaFuncSetAttribute(gemm_ps,  cudaFuncAttributeMaxDynamicSharedMemorySize, G_SMEM);
    cudaFuncSetAttribute(gemm_pk,  cudaFuncAttributeMaxDynamicSharedMemorySize, G_SMEM);
    cudaFuncSetAttribute(attn_tc,  cudaFuncAttributeMaxDynamicSharedMemorySize, ATTN_SMEM);

    float *h, *q, *k, *v, *x2, *x3, *part;
    unsigned *whi, *wlo;
    unsigned *hs_hi, *hs_lo, *es_hi, *es_lo, *as_hi, *as_lo;
    unsigned *x1_hi, *x1_lo, *x3_hi, *x3_lo, *in_hi, *in_lo;
    cudaGetSymbolAddress((void**)&h,  g_h);
    cudaGetSymbolAddress((void**)&q,  g_q);
    cudaGetSymbolAddress((void**)&k,  g_k);
    cudaGetSymbolAddress((void**)&v,  g_v);
    cudaGetSymbolAddress((void**)&x2, g_x2);
    cudaGetSymbolAddress((void**)&x3, g_x3);
    cudaGetSymbolAddress((void**)&part, g_part);
    cudaGetSymbolAddress((void**)&whi, g_whi);
    cudaGetSymbolAddress((void**)&wlo, g_wlo);
    cudaGetSymbolAddress((void**)&hs_hi, g_hs_hi);
    cudaGetSymbolAddress((void**)&hs_lo, g_hs_lo);
    cudaGetSymbolAddress((void**)&es_hi, g_es_hi);
    cudaGetSymbolAddress((void**)&es_lo, g_es_lo);
    cudaGetSymbolAddress((void**)&as_hi, g_as_hi);
    cudaGetSymbolAddress((void**)&as_lo, g_as_lo);
    cudaGetSymbolAddress((void**)&x1_hi, g_x1_hi);
    cudaGetSymbolAddress((void**)&x1_lo, g_x1_lo);
    cudaGetSymbolAddress((void**)&x3_hi, g_x3_hi);
    cudaGetSymbolAddress((void**)&x3_lo, g_x3_lo);
    cudaGetSymbolAddress((void**)&in_hi, g_in_hi);
    cudaGetSymbolAddress((void**)&in_lo, g_in_lo);

    cudaMemcpyAsync(h, hidden, (size_t)Mrows * Hc * sizeof(float),
                    cudaMemcpyDeviceToDevice, 0);

    // ---- arena layout (grouped by tensor, batched split across layers) ----
    const size_t FH2W  = (size_t)Hc * Fc / 2;            // 2097152
    const size_t SAQKV = 0;
    const size_t SAOUT = SAQKV + 6 * 3 * (size_t)HH2W;   // 9437184
    const size_t CAQKV = SAOUT + 6 * (size_t)HH2W;       // 12582912
    const size_t CAOUT = CAQKV + 6 * 3 * (size_t)HH2W;   // 22020096
    const size_t O1W   = CAOUT + 6 * (size_t)HH2W;       // 25165824
    const size_t FFW   = O1W   + 6 * (size_t)HH2W;       // 28311552
    const size_t O2W   = FFW   + 6 * FH2W;               // 40894464

    split_w<<<(int)((6 * 3 * (size_t)HH2W + 255) / 256), 256>>>(sa_qkv_w, whi + SAQKV, wlo + SAQKV, 6 * 3 * Hc / 2, Hc);
    split_w<<<(int)((6 * (size_t)HH2W + 255) / 256), 256>>>(sa_out_w, whi + SAOUT, wlo + SAOUT, 6 * Hc / 2, Hc);
    split_w<<<(int)((6 * 3 * (size_t)HH2W + 255) / 256), 256>>>(ca_qkv_w, whi + CAQKV, wlo + CAQKV, 6 * 3 * Hc / 2, Hc);
    split_w<<<(int)((6 * (size_t)HH2W + 255) / 256), 256>>>(ca_out_w, whi + CAOUT, wlo + CAOUT, 6 * Hc / 2, Hc);
    split_w<<<(int)((6 * (size_t)HH2W + 255) / 256), 256>>>(o1_w, whi + O1W, wlo + O1W, 6 * Hc / 2, Hc);
    split_w<<<(int)((6 * FH2W + 255) / 256), 256>>>(ffn_w, whi + FFW, wlo + FFW, 6 * Hc / 2, Fc);
    split_w<<<(int)((6 * FH2W + 255) / 256), 256>>>(o2_w, whi + O2W, wlo + O2W, 6 * Fc / 2, Hc);

    const int ACTW = Mrows * Hc / 2;
    split_act<<<(ACTW + 255) / 256, 256>>>((const float2*)hidden, hs_hi, hs_lo, ACTW);
    split_act<<<(ACTW + 255) / 256, 256>>>((const float2*)enc, es_hi, es_lo, ACTW);

    const dim3 gq(Hc / 128, Mrows / 128, 3);
    const dim3 g2(Hc / 128, Mrows / 128, 2);
    const dim3 g4(Hc / 128, Mrows / 128, 4);
    const dim3 gF(Fc / 128, Mrows / 128);
    const int attnBlocks = Bc * NHc * (Sc / 128);

    for (int i = 0; i < LAYERS; i++) {
        // ---- self attention ----
        gemm_qkv<<<gq, 256, G_SMEM>>>(hs_hi, hs_lo, hs_hi, hs_lo,
                                      whi + SAQKV + (size_t)i * 3 * HH2W,
                                      wlo + SAQKV + (size_t)i * 3 * HH2W,
                                      sa_qkv_b + (size_t)i * 3 * Hc, q, k, v);
        attn_tc<<<attnBlocks, 256, ATTN_SMEM>>>(q, k, v, amask, as_hi, as_lo);
        gemm_pk<<<g2, 256, G_SMEM>>>(as_hi, as_lo,
                                     whi + SAOUT + (size_t)i * HH2W,
                                     wlo + SAOUT + (size_t)i * HH2W, part, Hc);
        ln_red<<<Mrows, 256>>>(part, 2, sa_out_b + (size_t)i * Hc, h,
                               sa_ln + (size_t)i * 2 * Hc, nullptr, x1_hi, x1_lo);

        // ---- cross attention ----
        gemm_qkv<<<gq, 256, G_SMEM>>>(hs_hi, hs_lo, es_hi, es_lo,
                                      whi + CAQKV + (size_t)i * 3 * HH2W,
                                      wlo + CAQKV + (size_t)i * 3 * HH2W,
                                      ca_qkv_b + (size_t)i * 3 * Hc, q, k, v);
        attn_tc<<<attnBlocks, 256, ATTN_SMEM>>>(q, k, v, emask, as_hi, as_lo);
        gemm_pk<<<g2, 256, G_SMEM>>>(as_hi, as_lo,
                                     whi + CAOUT + (size_t)i * HH2W,
                                     wlo + CAOUT + (size_t)i * HH2W, part, Hc);
        ln_red<<<Mrows, 256>>>(part, 2, ca_out_b + (size_t)i * Hc, h,
                               ca_ln + (size_t)i * 2 * Hc, x2, nullptr, nullptr);

        // ---- output_1: x3 = LN(x1 @ o1_w + b + x2) ----
        gemm_pk<<<g2, 256, G_SMEM>>>(x1_hi, x1_lo,
                                     whi + O1W + (size_t)i * HH2W,
                                     wlo + O1W + (size_t)i * HH2W, part, Hc);
        ln_red<<<Mrows, 256>>>(part, 2, o1_b + (size_t)i * Hc, x2,
                               o1_ln + (size_t)i * 2 * Hc, x3, x3_hi, x3_lo);

        // ---- FFN ----
        gemm_ps<<<gF, 256, G_SMEM>>>(x3_hi, x3_lo,
                                     whi + FFW + (size_t)i * FH2W,
                                     wlo + FFW + (size_t)i * FH2W,
                                     ffn_b + (size_t)i * Fc, in_hi, in_lo, Fc, Hc, 1);
        gemm_pk<<<g4, 256, G_SMEM>>>(in_hi, in_lo,
                                     whi + O2W + (size_t)i * FH2W,
                                     wlo + O2W + (size_t)i * FH2W, part, Fc);
        ln_red<<<Mrows, 256>>>(part, 4, o2_b + (size_t)i * Hc, x3,
                               o2_ln + (size_t)i * 2 * Hc,
                               (i == LAYERS - 1) ? out : h,
                               (i == LAYERS - 1) ? nullptr : hs_hi,
                               (i == LAYERS - 1) ? nullptr : hs_lo);
    }
}

// round 16
// speedup vs baseline: 1.8219x; 1.0204x over previous
#include <cuda_runtime.h>
#include <cuda_bf16.h>
#include <math.h>
#include <stdint.h>

#define LAYERS 6
#define Hc 1024
#define NHc 16
#define Dc 64
#define Fc 4096
#define Bc 4
#define Sc 512
#define Mrows (Bc * Sc)
#define LN_EPS 1e-12f
#define GELU_C 0.7978845608028654f

// fp32 scratch
__device__ float g_h[Mrows * Hc];
__device__ float g_q[Mrows * Hc];
__device__ float g_k[Mrows * Hc];
__device__ float g_v[Mrows * Hc];
__device__ float g_qc[Mrows * Hc];
__device__ float g_kc[Mrows * Hc];
__device__ float g_vc[Mrows * Hc];
__device__ float g_x2[Mrows * Hc];
__device__ float g_x3[Mrows * Hc];
__device__ float g_part[4 * Mrows * Hc];   // split-K partials (<=4 slices)

// pre-split weight arenas (hi/lo bf16x2 words, pairs along K)
#define WARENA (53477376ULL)
__device__ unsigned g_whi[WARENA];
__device__ unsigned g_wlo[WARENA];

// pre-split activation word buffers [M][K/2]
__device__ unsigned g_hs_hi[Mrows * Hc / 2],  g_hs_lo[Mrows * Hc / 2];
__device__ unsigned g_es_hi[Mrows * Hc / 2],  g_es_lo[Mrows * Hc / 2];
__device__ unsigned g_as_hi[Mrows * Hc / 2],  g_as_lo[Mrows * Hc / 2];
__device__ unsigned g_ac_hi[Mrows * Hc / 2],  g_ac_lo[Mrows * Hc / 2];
__device__ unsigned g_x1_hi[Mrows * Hc / 2],  g_x1_lo[Mrows * Hc / 2];
__device__ unsigned g_x3_hi[Mrows * Hc / 2],  g_x3_lo[Mrows * Hc / 2];
__device__ unsigned g_in_hi[Mrows * Fc / 2],  g_in_lo[Mrows * Fc / 2];

// ---------------------------------------------------------------------------
// Helpers
// ---------------------------------------------------------------------------
__device__ __forceinline__ uint32_t smem_u32(const void* p) {
    uint32_t a;
    asm("{ .reg .u64 t; cvta.to.shared.u64 t, %1; cvt.u32.u64 %0, t; }" : "=r"(a) : "l"(p));
    return a;
}
__device__ __forceinline__ void bfsplit2(float x0, float x1, unsigned& hi, unsigned& lo) {
    unsigned h;
    asm("cvt.rn.bf16x2.f32 %0, %1, %2;" : "=r"(h) : "f"(x1), "f"(x0));
    float h0 = __uint_as_float(h << 16);
    float h1 = __uint_as_float(h & 0xffff0000u);
    unsigned l;
    asm("cvt.rn.bf16x2.f32 %0, %1, %2;" : "=r"(l) : "f"(x1 - h1), "f"(x0 - h0));
    hi = h; lo = l;
}
__device__ __forceinline__ void mma16(float* c, const unsigned* a, const unsigned* b) {
    asm("mma.sync.aligned.m16n8k16.row.col.f32.bf16.bf16.f32 "
        "{%0,%1,%2,%3}, {%4,%5,%6,%7}, {%8,%9}, {%0,%1,%2,%3};"
        : "+f"(c[0]), "+f"(c[1]), "+f"(c[2]), "+f"(c[3])
        : "r"(a[0]), "r"(a[1]), "r"(a[2]), "r"(a[3]), "r"(b[0]), "r"(b[1]));
}
__device__ __forceinline__ void cp16(uint32_t dst, const void* src) {
    asm volatile("cp.async.cg.shared.global [%0], [%1], 16;" :: "r"(dst), "l"(src));
}
__device__ __forceinline__ float gelu_new(float x) {
    float z = GELU_C * (x + 0.044715f * x * x * x);
    float e = __expf(2.f * z);
    float th = (e - 1.f) / (e + 1.f);
    return 0.5f * x * (1.0f + th);
}

// ---------------------------------------------------------------------------
// Split kernels
// ---------------------------------------------------------------------------
__global__ __launch_bounds__(256) void split_w(
    const float* __restrict__ src, unsigned* __restrict__ hi,
    unsigned* __restrict__ lo, int K2, int N)
{
    int idx = blockIdx.x * 256 + threadIdx.x;
    if (idx >= K2 * N) return;
    int k2 = idx / N, n = idx - k2 * N;
    float f0 = src[(size_t)(2 * k2) * N + n];
    float f1 = src[(size_t)(2 * k2 + 1) * N + n];
    unsigned h, l;
    bfsplit2(f0, f1, h, l);
    hi[idx] = h; lo[idx] = l;
}
__global__ __launch_bounds__(256) void split_act(
    const float2* __restrict__ src, unsigned* __restrict__ hi,
    unsigned* __restrict__ lo, int total)
{
    int idx = blockIdx.x * 256 + threadIdx.x;
    if (idx >= total) return;
    float2 f = src[idx];
    unsigned h, l;
    bfsplit2(f.x, f.y, h, l);
    hi[idx] = h; lo[idx] = l;
}

// ---------------------------------------------------------------------------
// Shared GEMM core: CTA 128x128, 16-k steps, 3-stage cp.async pipeline,
// 8 warps (2x4), warp tile 64x32.
// ---------------------------------------------------------------------------
#define STG_W 5248
#define STG_B 20992
#define G_SMEM (3 * STG_B)

__device__ __forceinline__ void gemm_core(
    const unsigned* __restrict__ Ahi, const unsigned* __restrict__ Alo,
    const unsigned* __restrict__ Whi, const unsigned* __restrict__ Wlo,
    int K2, int N, int kw0, int T, int bm, int bn,
    char* smem, float acc[4][4][4])
{
    unsigned* sw = (unsigned*)smem;
    const uint32_t sb = smem_u32(smem);
    const int tid = threadIdx.x, lane = tid & 31, warp = tid >> 5;
    const int wr = warp >> 2, wc = warp & 3;
    const int g = lane >> 2, tg = lane & 3;
    const int arow = tid >> 1, ahalf = tid & 1;
    const int br_ = tid >> 5, bc_ = tid & 31;

    auto issue = [&](int t) {
        const uint32_t st = sb + (uint32_t)(t % 3) * STG_B;
        const size_t ao = (size_t)(bm + arow) * K2 + kw0 + t * 8 + ahalf * 4;
        cp16(st + arow * 48 + ahalf * 16, Ahi + ao);
        cp16(st + 6144 + arow * 48 + ahalf * 16, Alo + ao);
        const size_t wo = (size_t)(kw0 + t * 8 + br_) * N + bn + bc_ * 4;
        cp16(st + 12288 + br_ * 544 + bc_ * 16, Whi + wo);
        cp16(st + 16640 + br_ * 544 + bc_ * 16, Wlo + wo);
        asm volatile("cp.async.commit_group;" ::: "memory");
    };
    auto compute = [&](int t) {
        const unsigned* S = sw + (size_t)(t % 3) * STG_W;
        unsigned ah[4][4], al_[4][4];
        #pragma unroll
        for (int i = 0; i < 4; i++) {
            const int rb = wr * 64 + i * 16 + g;
            ah[i][0]  = S[rb * 12 + tg];        ah[i][1]  = S[(rb + 8) * 12 + tg];
            ah[i][2]  = S[rb * 12 + tg + 4];    ah[i][3]  = S[(rb + 8) * 12 + tg + 4];
            al_[i][0] = S[1536 + rb * 12 + tg];      al_[i][1] = S[1536 + (rb + 8) * 12 + tg];
            al_[i][2] = S[1536 + rb * 12 + tg + 4];  al_[i][3] = S[1536 + (rb + 8) * 12 + tg + 4];
        }
        #pragma unroll
        for (int j = 0; j < 4; j++) {
            const int cb = wc * 32 + j * 8 + g;
            unsigned bh2[2], bl2[2];
            bh2[0] = S[3072 + tg * 136 + cb];       bh2[1] = S[3072 + (tg + 4) * 136 + cb];
            bl2[0] = S[4160 + tg * 136 + cb];       bl2[1] = S[4160 + (tg + 4) * 136 + cb];
            #pragma unroll
            for (int i = 0; i < 4; i++) {
                mma16(acc[i][j], ah[i],  bh2);
                mma16(acc[i][j], ah[i],  bl2);
                mma16(acc[i][j], al_[i], bh2);
            }
        }
    };

    issue(0);
    if (T > 1) issue(1);
    for (int t = 0; t < T; t++) {
        asm volatile("cp.async.wait_group 1;" ::: "memory");
        __syncthreads();
        compute(t);
        if (t + 2 < T) issue(t + 2);
        else asm volatile("cp.async.commit_group;" ::: "memory");
        __syncthreads();
    }
}

#define HH2W (Hc * Hc / 2)

// ---- fused 6-way QKV: z in {saQ,saK,saV,caQ,caK,caV} ----
__global__ __launch_bounds__(256, 2) void gemm_qkv6(
    const unsigned* __restrict__ hsh, const unsigned* __restrict__ hsl,
    const unsigned* __restrict__ esh, const unsigned* __restrict__ esl,
    const unsigned* __restrict__ wsah, const unsigned* __restrict__ wsal,
    const unsigned* __restrict__ wcah, const unsigned* __restrict__ wcal,
    const float* __restrict__ bsa, const float* __restrict__ bca,
    float* __restrict__ Oqs, float* __restrict__ Oks, float* __restrict__ Ovs,
    float* __restrict__ Oqc, float* __restrict__ Okc, float* __restrict__ Ovc)
{
    extern __shared__ char smem[];
    const int z = blockIdx.z;
    const int self = (z < 3) ? 1 : 0;
    const int wz = self ? z : (z - 3);
    const unsigned* Ahi = (z <= 3) ? hsh : esh;   // caQ uses layer input h
    const unsigned* Alo = (z <= 3) ? hsl : esl;
    const unsigned* Whi = (self ? wsah : wcah) + (size_t)wz * HH2W;
    const unsigned* Wlo = (self ? wsal : wcal) + (size_t)wz * HH2W;
    const float* bz = (self ? bsa : bca) + wz * Hc;
    const int bm = blockIdx.y * 128, bn = blockIdx.x * 128;

    float acc[4][4][4];
    #pragma unroll
    for (int i = 0; i < 4; i++)
        #pragma unroll
        for (int j = 0; j < 4; j++)
            #pragma unroll
            for (int r = 0; r < 4; r++) acc[i][j][r] = 0.f;

    gemm_core(Ahi, Alo, Whi, Wlo, Hc / 2, Hc, 0, Hc / 16, bm, bn, smem, acc);

    float* C = (z == 0) ? Oqs : (z == 1) ? Oks : (z == 2) ? Ovs
             : (z == 3) ? Oqc : (z == 4) ? Okc : Ovc;
    const int lane = threadIdx.x & 31, warp = threadIdx.x >> 5;
    const int wr = warp >> 2, wc = warp & 3, g = lane >> 2, tg = lane & 3;
    #pragma unroll
    for (int i = 0; i < 4; i++) {
        int row0 = bm + wr * 64 + i * 16 + g;
        #pragma unroll
        for (int j = 0; j < 4; j++) {
            int col = bn + wc * 32 + j * 8 + 2 * tg;
            float2 b2 = *(const float2*)(bz + col);
            *(float2*)(C + (size_t)row0 * Hc + col) =
                make_float2(acc[i][j][0] + b2.x, acc[i][j][1] + b2.y);
            *(float2*)(C + (size_t)(row0 + 8) * Hc + col) =
                make_float2(acc[i][j][2] + b2.x, acc[i][j][3] + b2.y);
        }
    }
}

// ---- direct GEMM with split epilogue (FFN-up) ----
__global__ __launch_bounds__(256, 2) void gemm_ps(
    const unsigned* __restrict__ Ahi, const unsigned* __restrict__ Alo,
    const unsigned* __restrict__ Whi, const unsigned* __restrict__ Wlo,
    const float* __restrict__ bias,
    unsigned* __restrict__ Chi, unsigned* __restrict__ Clo,
    int N, int K, int fuse_gelu)
{
    extern __shared__ char smem[];
    const int bm = blockIdx.y * 128, bn = blockIdx.x * 128;
    float acc[4][4][4];
    #pragma unroll
    for (int i = 0; i < 4; i++)
        #pragma unroll
        for (int j = 0; j < 4; j++)
            #pragma unroll
            for (int r = 0; r < 4; r++) acc[i][j][r] = 0.f;

    gemm_core(Ahi, Alo, Whi, Wlo, K / 2, N, 0, K / 16, bm, bn, smem, acc);

    const int lane = threadIdx.x & 31, warp = threadIdx.x >> 5;
    const int wr = warp >> 2, wc = warp & 3, g = lane >> 2, tg = lane & 3;
    #pragma unroll
    for (int i = 0; i < 4; i++) {
        int row0 = bm + wr * 64 + i * 16 + g;
        #pragma unroll
        for (int j = 0; j < 4; j++) {
            int col = bn + wc * 32 + j * 8 + 2 * tg;
            float2 b2 = *(const float2*)(bias + col);
            float v0 = acc[i][j][0] + b2.x, v1 = acc[i][j][1] + b2.y;
            float v2 = acc[i][j][2] + b2.x, v3 = acc[i][j][3] + b2.y;
            if (fuse_gelu) {
                v0 = gelu_new(v0); v1 = gelu_new(v1);
                v2 = gelu_new(v2); v3 = gelu_new(v3);
            }
            unsigned h0, l0, h1, l1;
            bfsplit2(v0, v1, h0, l0);
            bfsplit2(v2, v3, h1, l1);
            size_t w0 = (size_t)row0 * (N >> 1) + (col >> 1);
            size_t w1 = (size_t)(row0 + 8) * (N >> 1) + (col >> 1);
            Chi[w0] = h0; Clo[w0] = l0;
            Chi[w1] = h1; Clo[w1] = l1;
        }
    }
}

// ---- split-K GEMM -> fp32 partial slice z ----
__global__ __launch_bounds__(256, 2) void gemm_pk(
    const unsigned* __restrict__ Ahi, const unsigned* __restrict__ Alo,
    const unsigned* __restrict__ Whi, const unsigned* __restrict__ Wlo,
    float* __restrict__ P, int K)
{
    extern __shared__ char smem[];
    const int z = blockIdx.z, Z = gridDim.z;
    const int Ks = K / Z;
    const int bm = blockIdx.y * 128, bn = blockIdx.x * 128;
    float acc[4][4][4];
    #pragma unroll
    for (int i = 0; i < 4; i++)
        #pragma unroll
        for (int j = 0; j < 4; j++)
            #pragma unroll
            for (int r = 0; r < 4; r++) acc[i][j][r] = 0.f;

    gemm_core(Ahi, Alo, Whi, Wlo, K / 2, Hc, z * (Ks / 2), Ks / 16, bm, bn, smem, acc);

    float* Pz = P + (size_t)z * Mrows * Hc;
    const int lane = threadIdx.x & 31, warp = threadIdx.x >> 5;
    const int wr = warp >> 2, wc = warp & 3, g = lane >> 2, tg = lane & 3;
    #pragma unroll
    for (int i = 0; i < 4; i++) {
        int row0 = bm + wr * 64 + i * 16 + g;
        #pragma unroll
        for (int j = 0; j < 4; j++) {
            int col = bn + wc * 32 + j * 8 + 2 * tg;
            *(float2*)(Pz + (size_t)row0 * Hc + col) = make_float2(acc[i][j][0], acc[i][j][1]);
            *(float2*)(Pz + (size_t)(row0 + 8) * Hc + col) = make_float2(acc[i][j][2], acc[i][j][3]);
        }
    }
}

// ---- fused dual out-projection split-K: z01=self, z23=cross ----
__global__ __launch_bounds__(256, 2) void gemm_pk2(
    const unsigned* __restrict__ ash, const unsigned* __restrict__ asl,
    const unsigned* __restrict__ ach, const unsigned* __restrict__ acl,
    const unsigned* __restrict__ wsh, const unsigned* __restrict__ wsl,
    const unsigned* __restrict__ wch, const unsigned* __restrict__ wcl,
    float* __restrict__ P)
{
    extern __shared__ char smem[];
    const int z = blockIdx.z;
    const int sel = z >> 1, zz = z & 1;
    const unsigned* Ahi = sel ? ach : ash;
    const unsigned* Alo = sel ? acl : asl;
    const unsigned* Whi = sel ? wch : wsh;
    const unsigned* Wlo = sel ? wcl : wsl;
    const int bm = blockIdx.y * 128, bn = blockIdx.x * 128;
    float acc[4][4][4];
    #pragma unroll
    for (int i = 0; i < 4; i++)
        #pragma unroll
        for (int j = 0; j < 4; j++)
            #pragma unroll
            for (int r = 0; r < 4; r++) acc[i][j][r] = 0.f;

    gemm_core(Ahi, Alo, Whi, Wlo, Hc / 2, Hc, zz * (Hc / 4), Hc / 32, bm, bn, smem, acc);

    float* Pz = P + (size_t)z * Mrows * Hc;
    const int lane = threadIdx.x & 31, warp = threadIdx.x >> 5;
    const int wr = warp >> 2, wc = warp & 3, g = lane >> 2, tg = lane & 3;
    #pragma unroll
    for (int i = 0; i < 4; i++) {
        int row0 = bm + wr * 64 + i * 16 + g;
        #pragma unroll
        for (int j = 0; j < 4; j++) {
            int col = bn + wc * 32 + j * 8 + 2 * tg;
            *(float2*)(Pz + (size_t)row0 * Hc + col) = make_float2(acc[i][j][0], acc[i][j][1]);
            *(float2*)(Pz + (size_t)(row0 + 8) * Hc + col) = make_float2(acc[i][j][2], acc[i][j][3]);
        }
    }
}

// ---------------------------------------------------------------------------
// Reductions + LayerNorm
// ---------------------------------------------------------------------------
__device__ __forceinline__ float block_sum_256(float v) {
    __shared__ float sh[8];
    #pragma unroll
    for (int o = 16; o > 0; o >>= 1) v += __shfl_xor_sync(0xffffffffu, v, o);
    __syncthreads();
    if ((threadIdx.x & 31) == 0) sh[threadIdx.x >> 5] = v;
    __syncthreads();
    float t = sh[0];
    #pragma unroll
    for (int i = 1; i < 8; i++) t += sh[i];
    return t;
}

__device__ __forceinline__ void ln_body(
    int row, const float* P, int Z, const float* bias, const float* add,
    const float* lnw, float* outF, unsigned* ohi, unsigned* olo)
{
    const int tid = threadIdx.x;
    const size_t MN = (size_t)Mrows * Hc;
    float4 v = ((const float4*)(P + (size_t)row * Hc))[tid];
    for (int z = 1; z < Z; z++) {
        float4 p = ((const float4*)(P + z * MN + (size_t)row * Hc))[tid];
        v.x += p.x; v.y += p.y; v.z += p.z; v.w += p.w;
    }
    float4 b4 = ((const float4*)bias)[tid];
    float4 a4 = ((const float4*)(add + (size_t)row * Hc))[tid];
    v.x += b4.x + a4.x; v.y += b4.y + a4.y; v.z += b4.z + a4.z; v.w += b4.w + a4.w;

    float s = v.x + v.y + v.z + v.w;
    s = block_sum_256(s);
    const float mean = s * (1.f / Hc);
    float dx = v.x - mean, dy = v.y - mean, dz = v.z - mean, dw = v.w - mean;
    float q = dx * dx + dy * dy + dz * dz + dw * dw;
    q = block_sum_256(q);
    const float inv = rsqrtf(q * (1.f / Hc) + LN_EPS);
    float4 gm = ((const float4*)lnw)[tid];
    float4 bt = ((const float4*)(lnw + Hc))[tid];
    float y0 = dx * inv * gm.x + bt.x;
    float y1 = dy * inv * gm.y + bt.y;
    float y2 = dz * inv * gm.z + bt.z;
    float y3 = dw * inv * gm.w + bt.w;
    if (outF)
        ((float4*)(outF + (size_t)row * Hc))[tid] = make_float4(y0, y1, y2, y3);
    if (ohi) {
        unsigned h0, l0, h1, l1;
        bfsplit2(y0, y1, h0, l0);
        bfsplit2(y2, y3, h1, l1);
        ((uint2*)(ohi + (size_t)row * (Hc / 2)))[tid] = make_uint2(h0, h1);
        ((uint2*)(olo + (size_t)row * (Hc / 2)))[tid] = make_uint2(l0, l1);
    }
}

__global__ __launch_bounds__(256) void ln_red(
    const float* __restrict__ P, int Z,
    const float* __restrict__ bias, const float* __restrict__ add,
    const float* __restrict__ lnw,
    float* __restrict__ outF, unsigned* __restrict__ ohi, unsigned* __restrict__ olo)
{
    ln_body(blockIdx.x, P, Z, bias, add, lnw, outF, ohi, olo);
}

// dual: path0 = self (part 0..1 -> x1 split), path1 = cross (part 2..3 -> x2 fp32)
__global__ __launch_bounds__(256) void ln_red2(
    const float* __restrict__ P,
    const float* __restrict__ bsa, const float* __restrict__ bca,
    const float* __restrict__ add,
    const float* __restrict__ lnsa, const float* __restrict__ lnca,
    unsigned* __restrict__ x1hi, unsigned* __restrict__ x1lo,
    float* __restrict__ x2)
{
    const int row = blockIdx.x & (Mrows - 1);
    const int sel = blockIdx.x >> 11;
    if (sel == 0)
        ln_body(row, P, 2, bsa, add, lnsa, nullptr, x1hi, x1lo);
    else
        ln_body(row, P + 2 * (size_t)Mrows * Hc, 2, bca, add, lnca, x2, nullptr, nullptr);
}

// ---------------------------------------------------------------------------
// Fused self+cross FlashAttention (bf16x2 split, m16n8k16)
// ---------------------------------------------------------------------------
#define LDQ 36
#define LDK 72
#define LDV 72
#define ATTN_SMEM ((2 * 128 * LDQ + 2 * 32 * LDK + 2 * 32 * LDV) * 4 + Sc * 4)

__global__ __launch_bounds__(256) void attn_tc2(
    const float* __restrict__ Qs, const float* __restrict__ Ks_,
    const float* __restrict__ Vs,
    const float* __restrict__ Qc, const float* __restrict__ Kc,
    const float* __restrict__ Vc,
    const int* __restrict__ amask, const int* __restrict__ emask,
    unsigned* __restrict__ ashi, unsigned* __restrict__ aslo,
    unsigned* __restrict__ achi, unsigned* __restrict__ aclo)
{
    extern __shared__ unsigned sm_a[];
    unsigned* Qh = sm_a;
    unsigned* Ql = Qh + 128 * LDQ;
    unsigned* Kh = Ql + 128 * LDQ;
    unsigned* Kl = Kh + 32 * LDK;
    unsigned* Vh = Kl + 32 * LDK;
    unsigned* Vl = Vh + 32 * LDV;
    float* madd = (float*)(Vl + 32 * LDV);

    const int sel = blockIdx.x >> 8;
    const int inner = blockIdx.x & 255;
    const float* Q   = sel ? Qc : Qs;
    const float* Kin = sel ? Kc : Ks_;
    const float* Vin = sel ? Vc : Vs;
    const int* mask  = sel ? emask : amask;
    unsigned* Ohi    = sel ? achi : ashi;
    unsigned* Olo    = sel ? aclo : aslo;

    const int tid = threadIdx.x, lane = tid & 31, warp = tid >> 5;
    const int g = lane >> 2, tg = lane & 3;
    const int qt = inner & 3;
    const int n  = (inner >> 2) & 15;
    const int b  = inner >> 6;

    for (int j = tid; j < Sc; j += 256)
        madd[j] = mask[b * Sc + j] ? 0.f : -10000.f;

    {
        int r = tid >> 1, d0 = (tid & 1) * 32;
        const float* qp = Q + (size_t)(b * Sc + qt * 128 + r) * Hc + n * Dc + d0;
        #pragma unroll
        for (int i = 0; i < 32; i += 8) {
            float4 u = *(const float4*)(qp + i);
            float4 w = *(const float4*)(qp + i + 4);
            unsigned h0, l0, h1, l1, h2, l2, h3, l3;
            bfsplit2(u.x, u.y, h0, l0); bfsplit2(u.z, u.w, h1, l1);
            bfsplit2(w.x, w.y, h2, l2); bfsplit2(w.z, w.w, h3, l3);
            *(uint4*)&Qh[r * LDQ + ((d0 + i) >> 1)] = make_uint4(h0, h1, h2, h3);
            *(uint4*)&Ql[r * LDQ + ((d0 + i) >> 1)] = make_uint4(l0, l1, l2, l3);
        }
    }
    __syncthreads();

    float o[8][4];
    #pragma unroll
    for (int j = 0; j < 8; j++)
        #pragma unroll
        for (int r = 0; r < 4; r++) o[j][r] = 0.f;
    float m_run[2] = {-1e30f, -1e30f};
    float l_run[2] = {0.f, 0.f};

    for (int kv = 0; kv < Sc; kv += 64) {
        {
            int r = tid >> 2, d0 = (tid & 3) * 16;
            const float* kpp = Kin + (size_t)(b * Sc + kv + r) * Hc + n * Dc + d0;
            float4 u = *(const float4*)(kpp);
            float4 w = *(const float4*)(kpp + 4);
            float4 x = *(const float4*)(kpp + 8);
            float4 y = *(const float4*)(kpp + 12);
            float pv[16] = {u.x, u.y, u.z, u.w, w.x, w.y, w.z, w.w,
                            x.x, x.y, x.z, x.w, y.x, y.y, y.z, y.w};
            #pragma unroll
            for (int p = 0; p < 8; p++) {
                unsigned h, l;
                bfsplit2(pv[2 * p], pv[2 * p + 1], h, l);
                Kh[((d0 >> 1) + p) * LDK + r] = h;
                Kl[((d0 >> 1) + p) * LDK + r] = l;
            }
            int kp2 = tid >> 3, dv0 = (tid & 7) * 8;
            const float* v0p = Vin + (size_t)(b * Sc + kv + 2 * kp2) * Hc + n * Dc + dv0;
            float4 a0 = *(const float4*)(v0p);
            float4 a1 = *(const float4*)(v0p + 4);
            float4 b0 = *(const float4*)(v0p + Hc);
            float4 b1 = *(const float4*)(v0p + Hc + 4);
            unsigned hh[8], ll[8];
            bfsplit2(a0.x, b0.x, hh[0], ll[0]); bfsplit2(a0.y, b0.y, hh[1], ll[1]);
            bfsplit2(a0.z, b0.z, hh[2], ll[2]); bfsplit2(a0.w, b0.w, hh[3], ll[3]);
            bfsplit2(a1.x, b1.x, hh[4], ll[4]); bfsplit2(a1.y, b1.y, hh[5], ll[5]);
            bfsplit2(a1.z, b1.z, hh[6], ll[6]); bfsplit2(a1.w, b1.w, hh[7], ll[7]);
            *(uint4*)&Vh[kp2 * LDV + dv0]     = make_uint4(hh[0], hh[1], hh[2], hh[3]);
            *(uint4*)&Vh[kp2 * LDV + dv0 + 4] = make_uint4(hh[4], hh[5], hh[6], hh[7]);
            *(uint4*)&Vl[kp2 * LDV + dv0]     = make_uint4(ll[0], ll[1], ll[2], ll[3]);
            *(uint4*)&Vl[kp2 * LDV + dv0 + 4] = make_uint4(ll[4], ll[5], ll[6], ll[7]);
        }
        __syncthreads();

        float s[8][4];
        #pragma unroll
        for (int j = 0; j < 8; j++)
            #pragma unroll
            for (int r = 0; r < 4; r++) s[j][r] = 0.f;
        #pragma unroll
        for (int kk2 = 0; kk2 < 32; kk2 += 8) {
            int rb = warp * 16 + g;
            unsigned qh[4], ql_[4];
            qh[0] = Qh[rb * LDQ + kk2 + tg];        qh[1] = Qh[(rb + 8) * LDQ + kk2 + tg];
            qh[2] = Qh[rb * LDQ + kk2 + tg + 4];    qh[3] = Qh[(rb + 8) * LDQ + kk2 + tg + 4];
            ql_[0] = Ql[rb * LDQ + kk2 + tg];       ql_[1] = Ql[(rb + 8) * LDQ + kk2 + tg];
            ql_[2] = Ql[rb * LDQ + kk2 + tg + 4];   ql_[3] = Ql[(rb + 8) * LDQ + kk2 + tg + 4];
            #pragma unroll
            for (int j = 0; j < 8; j++) {
                unsigned kh2[2], kl2[2];
                kh2[0] = Kh[(kk2 + tg) * LDK + j * 8 + g];
                kh2[1] = Kh[(kk2 + tg + 4) * LDK + j * 8 + g];
                kl2[0] = Kl[(kk2 + tg) * LDK + j * 8 + g];
                kl2[1] = Kl[(kk2 + tg + 4) * LDK + j * 8 + g];
                mma16(s[j], qh, kh2);
                mma16(s[j], qh, kl2);
                mma16(s[j], ql_, kh2);
            }
        }

        float corr[2];
        #pragma unroll
        for (int r2 = 0; r2 < 2; r2++) {
            float mx = m_run[r2];
            #pragma unroll
            for (int j = 0; j < 8; j++)
                #pragma unroll
                for (int c = 0; c < 2; c++) {
                    float val = s[j][r2 * 2 + c] * 0.125f + madd[kv + j * 8 + 2 * tg + c];
                    s[j][r2 * 2 + c] = val;
                    mx = fmaxf(mx, val);
                }
            mx = fmaxf(mx, __shfl_xor_sync(0xffffffffu, mx, 1));
            mx = fmaxf(mx, __shfl_xor_sync(0xffffffffu, mx, 2));
            corr[r2] = __expf(m_run[r2] - mx);
            m_run[r2] = mx;
            float rs = 0.f;
            #pragma unroll
            for (int j = 0; j < 8; j++)
                #pragma unroll
                for (int c = 0; c < 2; c++) {
                    float e = __expf(s[j][r2 * 2 + c] - mx);
                    s[j][r2 * 2 + c] = e;
                    rs += e;
                }
            rs += __shfl_xor_sync(0xffffffffu, rs, 1);
            rs += __shfl_xor_sync(0xffffffffu, rs, 2);
            l_run[r2] = l_run[r2] * corr[r2] + rs;
        }
        #pragma unroll
        for (int j = 0; j < 8; j++) {
            o[j][0] *= corr[0]; o[j][1] *= corr[0];
            o[j][2] *= corr[1]; o[j][3] *= corr[1];
        }

        #pragma unroll
        for (int kf = 0; kf < 4; kf++) {
            unsigned ph[4], pl[4];
            bfsplit2(s[2 * kf][0],     s[2 * kf][1],     ph[0], pl[0]);
            bfsplit2(s[2 * kf][2],     s[2 * kf][3],     ph[1], pl[1]);
            bfsplit2(s[2 * kf + 1][0], s[2 * kf + 1][1], ph[2], pl[2]);
            bfsplit2(s[2 * kf + 1][2], s[2 * kf + 1][3], ph[3], pl[3]);
            #pragma unroll
            for (int j = 0; j < 8; j++) {
                unsigned vh2[2], vl2[2];
                vh2[0] = Vh[(kf * 8 + tg) * LDV + j * 8 + g];
                vh2[1] = Vh[(kf * 8 + tg + 4) * LDV + j * 8 + g];
                vl2[0] = Vl[(kf * 8 + tg) * LDV + j * 8 + g];
                vl2[1] = Vl[(kf * 8 + tg + 4) * LDV + j * 8 + g];
                mma16(o[j], ph, vh2);
                mma16(o[j], ph, vl2);
                mma16(o[j], pl, vh2);
            }
        }
        __syncthreads();
    }

    float inv0 = 1.f / l_run[0], inv1 = 1.f / l_run[1];
    int row0 = b * Sc + qt * 128 + warp * 16 + g;
    #pragma unroll
    for (int j = 0; j < 8; j++) {
        int wcol = n * 32 + j * 4 + tg;
        unsigned h0, l0, h1, l1;
        bfsplit2(o[j][0] * inv0, o[j][1] * inv0, h0, l0);
        bfsplit2(o[j][2] * inv1, o[j][3] * inv1, h1, l1);
        Ohi[(size_t)row0 * (Hc / 2) + wcol] = h0;
        Olo[(size_t)row0 * (Hc / 2) + wcol] = l0;
        Ohi[(size_t)(row0 + 8) * (Hc / 2) + wcol] = h1;
        Olo[(size_t)(row0 + 8) * (Hc / 2) + wcol] = l1;
    }
}

// ---------------------------------------------------------------------------
// Orchestration
// ---------------------------------------------------------------------------
extern "C" void kernel_launch(void* const* d_in, const int* in_sizes, int n_in,
                              void* d_out, int out_size)
{
    const float* hidden   = (const float*)d_in[0];
    const float* enc      = (const float*)d_in[1];
    const int*   amask    = (const int*)d_in[2];
    const int*   emask    = (const int*)d_in[3];
    const float* sa_qkv_w = (const float*)d_in[4];
    const float* sa_qkv_b = (const float*)d_in[5];
    const float* sa_out_w = (const float*)d_in[6];
    const float* sa_out_b = (const float*)d_in[7];
    const float* sa_ln    = (const float*)d_in[8];
    const float* ca_qkv_w = (const float*)d_in[9];
    const float* ca_qkv_b = (const float*)d_in[10];
    const float* ca_out_w = (const float*)d_in[11];
    const float* ca_out_b = (const float*)d_in[12];
    const float* ca_ln    = (const float*)d_in[13];
    const float* o1_w     = (const float*)d_in[14];
    const float* o1_b     = (const float*)d_in[15];
    const float* o1_ln    = (const float*)d_in[16];
    const float* ffn_w    = (const float*)d_in[17];
    const float* ffn_b    = (const float*)d_in[18];
    const float* o2_w     = (const float*)d_in[19];
    const float* o2_b     = (const float*)d_in[20];
    const float* o2_ln    = (const float*)d_in[21];
    float* out = (float*)d_out;

    cudaFuncSetAttribute(gemm_qkv6, cudaFuncAttributeMaxDynamicSharedMemorySize, G_SMEM);
    cudaFuncSetAttribute(gemm_ps,   cudaFuncAttributeMaxDynamicSharedMemorySize, G_SMEM);
    cudaFuncSetAttribute(gemm_pk,   cudaFuncAttributeMaxDynamicSharedMemorySize, G_SMEM);
    cudaFuncSetAttribute(gemm_pk2,  cudaFuncAttributeMaxDynamicSharedMemorySize, G_SMEM);
    cudaFuncSetAttribute(attn_tc2,  cudaFuncAttributeMaxDynamicSharedMemorySize, ATTN_SMEM);

    float *h, *q, *k, *v, *qc, *kc, *vc, *x2, *x3, *part;
    unsigned *whi, *wlo;
    unsigned *hs_hi, *hs_lo, *es_hi, *es_lo, *as_hi, *as_lo, *ac_hi, *ac_lo;
    unsigned *x1_hi, *x1_lo, *x3_hi, *x3_lo, *in_hi, *in_lo;
    cudaGetSymbolAddress((void**)&h,  g_h);
    cudaGetSymbolAddress((void**)&q,  g_q);
    cudaGetSymbolAddress((void**)&k,  g_k);
    cudaGetSymbolAddress((void**)&v,  g_v);
    cudaGetSymbolAddress((void**)&qc, g_qc);
    cudaGetSymbolAddress((void**)&kc, g_kc);
    cudaGetSymbolAddress((void**)&vc, g_vc);
    cudaGetSymbolAddress((void**)&x2, g_x2);
    cudaGetSymbolAddress((void**)&x3, g_x3);
    cudaGetSymbolAddress((void**)&part, g_part);
    cudaGetSymbolAddress((void**)&whi, g_whi);
    cudaGetSymbolAddress((void**)&wlo, g_wlo);
    cudaGetSymbolAddress((void**)&hs_hi, g_hs_hi);
    cudaGetSymbolAddress((void**)&hs_lo, g_hs_lo);
    cudaGetSymbolAddress((void**)&es_hi, g_es_hi);
    cudaGetSymbolAddress((void**)&es_lo, g_es_lo);
    cudaGetSymbolAddress((void**)&as_hi, g_as_hi);
    cudaGetSymbolAddress((void**)&as_lo, g_as_lo);
    cudaGetSymbolAddress((void**)&ac_hi, g_ac_hi);
    cudaGetSymbolAddress((void**)&ac_lo, g_ac_lo);
    cudaGetSymbolAddress((void**)&x1_hi, g_x1_hi);
    cudaGetSymbolAddress((void**)&x1_lo, g_x1_lo);
    cudaGetSymbolAddress((void**)&x3_hi, g_x3_hi);
    cudaGetSymbolAddress((void**)&x3_lo, g_x3_lo);
    cudaGetSymbolAddress((void**)&in_hi, g_in_hi);
    cudaGetSymbolAddress((void**)&in_lo, g_in_lo);

    cudaMemcpyAsync(h, hidden, (size_t)Mrows * Hc * sizeof(float),
                    cudaMemcpyDeviceToDevice, 0);

    // ---- arena layout ----
    const size_t FH2W  = (size_t)Hc * Fc / 2;
    const size_t SAQKV = 0;
    const size_t SAOUT = SAQKV + 6 * 3 * (size_t)HH2W;
    const size_t CAQKV = SAOUT + 6 * (size_t)HH2W;
    const size_t CAOUT = CAQKV + 6 * 3 * (size_t)HH2W;
    const size_t O1W   = CAOUT + 6 * (size_t)HH2W;
    const size_t FFW   = O1W   + 6 * (size_t)HH2W;
    const size_t O2W   = FFW   + 6 * FH2W;

    split_w<<<(int)((6 * 3 * (size_t)HH2W + 255) / 256), 256>>>(sa_qkv_w, whi + SAQKV, wlo + SAQKV, 6 * 3 * Hc / 2, Hc);
    split_w<<<(int)((6 * (size_t)HH2W + 255) / 256), 256>>>(sa_out_w, whi + SAOUT, wlo + SAOUT, 6 * Hc / 2, Hc);
    split_w<<<(int)((6 * 3 * (size_t)HH2W + 255) / 256), 256>>>(ca_qkv_w, whi + CAQKV, wlo + CAQKV, 6 * 3 * Hc / 2, Hc);
    split_w<<<(int)((6 * (size_t)HH2W + 255) / 256), 256>>>(ca_out_w, whi + CAOUT, wlo + CAOUT, 6 * Hc / 2, Hc);
    split_w<<<(int)((6 * (size_t)HH2W + 255) / 256), 256>>>(o1_w, whi + O1W, wlo + O1W, 6 * Hc / 2, Hc);
    split_w<<<(int)((6 * FH2W + 255) / 256), 256>>>(ffn_w, whi + FFW, wlo + FFW, 6 * Hc / 2, Fc);
    split_w<<<(int)((6 * FH2W + 255) / 256), 256>>>(o2_w, whi + O2W, wlo + O2W, 6 * Fc / 2, Hc);

    const int ACTW = Mrows * Hc / 2;
    split_act<<<(ACTW + 255) / 256, 256>>>((const float2*)hidden, hs_hi, hs_lo, ACTW);
    split_act<<<(ACTW + 255) / 256, 256>>>((const float2*)enc, es_hi, es_lo, ACTW);

    const dim3 gq6(Hc / 128, Mrows / 128, 6);
    const dim3 g2(Hc / 128, Mrows / 128, 2);
    const dim3 g4a(Hc / 128, Mrows / 128, 4);
    const dim3 gF(Fc / 128, Mrows / 128);

    for (int i = 0; i < LAYERS; i++) {
        const size_t saq = SAQKV + (size_t)i * 3 * HH2W;
        const size_t caq = CAQKV + (size_t)i * 3 * HH2W;
        gemm_qkv6<<<gq6, 256, G_SMEM>>>(hs_hi, hs_lo, es_hi, es_lo,
                                        whi + saq, wlo + saq, whi + caq, wlo + caq,
                                        sa_qkv_b + (size_t)i * 3 * Hc,
                                        ca_qkv_b + (size_t)i * 3 * Hc,
                                        q, k, v, qc, kc, vc);
        attn_tc2<<<512, 256, ATTN_SMEM>>>(q, k, v, qc, kc, vc, amask, emask,
                                          as_hi, as_lo, ac_hi, ac_lo);
        gemm_pk2<<<g4a, 256, G_SMEM>>>(as_hi, as_lo, ac_hi, ac_lo,
                                       whi + SAOUT + (size_t)i * HH2W,
                                       wlo + SAOUT + (size_t)i * HH2W,
                                       whi + CAOUT + (size_t)i * HH2W,
                                       wlo + CAOUT + (size_t)i * HH2W, part);
        ln_red2<<<2 * Mrows, 256>>>(part, sa_out_b + (size_t)i * Hc,
                                    ca_out_b + (size_t)i * Hc, h,
                                    sa_ln + (size_t)i * 2 * Hc,
                                    ca_ln + (size_t)i * 2 * Hc,
                                    x1_hi, x1_lo, x2);

        gemm_pk<<<g2, 256, G_SMEM>>>(x1_hi, x1_lo,
                                     whi + O1W + (size_t)i * HH2W,
                                     wlo + O1W + (size_t)i * HH2W, part, Hc);
        ln_red<<<Mrows, 256>>>(part, 2, o1_b + (size_t)i * Hc, x2,
                               o1_ln + (size_t)i * 2 * Hc, x3, x3_hi, x3_lo);

        gemm_ps<<<gF, 256, G_SMEM>>>(x3_hi, x3_lo,
                                     whi + FFW + (size_t)i * FH2W,
                                     wlo + FFW + (size_t)i * FH2W,
                                     ffn_b + (size_t)i * Fc, in_hi, in_lo, Fc, Hc, 1);
        gemm_pk<<<g4a, 256, G_SMEM>>>(in_hi, in_lo,
                                      whi + O2W + (size_t)i * FH2W,
                                      wlo + O2W + (size_t)i * FH2W, part, Fc);
        ln_red<<<Mrows, 256>>>(part, 4, o2_b + (size_t)i * Hc, x3,
                               o2_ln + (size_t)i * 2 * Hc,
                               (i == LAYERS - 1) ? out : h,
                               (i == LAYERS - 1) ? nullptr : hs_hi,
                               (i == LAYERS - 1) ? nullptr : hs_lo);
    }
}

// round 17
// speedup vs baseline: 1.8846x; 1.0344x over previous
#include <cuda_runtime.h>
#include <cuda_bf16.h>
#include <math.h>
#include <stdint.h>

#define LAYERS 6
#define Hc 1024
#define NHc 16
#define Dc 64
#define Fc 4096
#define Bc 4
#define Sc 512
#define Mrows (Bc * Sc)
#define LN_EPS 1e-12f
#define GELU_C 0.7978845608028654f

// fp32 scratch
__device__ float g_h[Mrows * Hc];
__device__ float g_q[Mrows * Hc];
__device__ float g_k[Mrows * Hc];
__device__ float g_v[Mrows * Hc];
__device__ float g_qc[Mrows * Hc];
__device__ float g_kc[Mrows * Hc];
__device__ float g_vc[Mrows * Hc];
__device__ float g_x2[Mrows * Hc];
__device__ float g_x3[Mrows * Hc];
__device__ float g_part[4 * Mrows * Hc];

// pre-split weight arenas (hi/lo, fragment-packed words)
#define WARENA (53477376ULL)
__device__ unsigned g_whi[WARENA];
__device__ unsigned g_wlo[WARENA];

// pre-split activation word buffers (fragment-packed)
__device__ unsigned g_hs_hi[Mrows * Hc / 2],  g_hs_lo[Mrows * Hc / 2];
__device__ unsigned g_es_hi[Mrows * Hc / 2],  g_es_lo[Mrows * Hc / 2];
__device__ unsigned g_as_hi[Mrows * Hc / 2],  g_as_lo[Mrows * Hc / 2];
__device__ unsigned g_ac_hi[Mrows * Hc / 2],  g_ac_lo[Mrows * Hc / 2];
__device__ unsigned g_x1_hi[Mrows * Hc / 2],  g_x1_lo[Mrows * Hc / 2];
__device__ unsigned g_x3_hi[Mrows * Hc / 2],  g_x3_lo[Mrows * Hc / 2];
__device__ unsigned g_in_hi[Mrows * Fc / 2],  g_in_lo[Mrows * Fc / 2];

// ---------------------------------------------------------------------------
// Helpers
// ---------------------------------------------------------------------------
__device__ __forceinline__ uint32_t smem_u32(const void* p) {
    uint32_t a;
    asm("{ .reg .u64 t; cvta.to.shared.u64 t, %1; cvt.u32.u64 %0, t; }" : "=r"(a) : "l"(p));
    return a;
}
__device__ __forceinline__ void bfsplit2(float x0, float x1, unsigned& hi, unsigned& lo) {
    unsigned h;
    asm("cvt.rn.bf16x2.f32 %0, %1, %2;" : "=r"(h) : "f"(x1), "f"(x0));
    float h0 = __uint_as_float(h << 16);
    float h1 = __uint_as_float(h & 0xffff0000u);
    unsigned l;
    asm("cvt.rn.bf16x2.f32 %0, %1, %2;" : "=r"(l) : "f"(x1 - h1), "f"(x0 - h0));
    hi = h; lo = l;
}
__device__ __forceinline__ void mma16(float* c, const unsigned* a, const unsigned* b) {
    asm("mma.sync.aligned.m16n8k16.row.col.f32.bf16.bf16.f32 "
        "{%0,%1,%2,%3}, {%4,%5,%6,%7}, {%8,%9}, {%0,%1,%2,%3};"
        : "+f"(c[0]), "+f"(c[1]), "+f"(c[2]), "+f"(c[3])
        : "r"(a[0]), "r"(a[1]), "r"(a[2]), "r"(a[3]), "r"(b[0]), "r"(b[1]));
}
__device__ __forceinline__ void cp16(uint32_t dst, const void* src) {
    asm volatile("cp.async.cg.shared.global [%0], [%1], 16;" :: "r"(dst), "l"(src));
}
__device__ __forceinline__ float gelu_new(float x) {
    float z = GELU_C * (x + 0.044715f * x * x * x);
    float e = __expf(2.f * z);
    float th = (e - 1.f) / (e + 1.f);
    return 0.5f * x * (1.0f + th);
}

// Fragment-packed activation index: word (m, k2) of an [M][K2] word matrix.
// Layout: [m16][chunk c=k2/8] blocks of 128 words; within: lane*4 + j,
// lane = (m&7)*4 + (k2&3), j = ((m>>3)&1) + 2*((k2>>2)&1).
__device__ __forceinline__ size_t aidx(int m, int k2, int K2) {
    int c = k2 >> 3, w = k2 & 7;
    int j = ((m >> 3) & 1) + ((w >> 2) << 1);
    int lane = ((m & 7) << 2) | (w & 3);
    return ((size_t)(m >> 4) * (K2 >> 3) + c) * 128 + lane * 4 + j;
}
// Fragment-packed weight index: word (k2, n) of a [K2][N] word matrix.
// Layout: [chunk][n] groups of 8 words: (tg pair) = tg*2 + (w>>2).
__device__ __forceinline__ size_t widx(int k2, int n, int N) {
    int c = k2 >> 3, w = k2 & 7;
    return ((size_t)c * N + n) * 8 + ((w & 3) << 1) + (w >> 2);
}

// ---------------------------------------------------------------------------
// Split kernels (emit fragment-packed layouts)
// ---------------------------------------------------------------------------
__global__ __launch_bounds__(256) void split_w(
    const float* __restrict__ src, unsigned* __restrict__ hi,
    unsigned* __restrict__ lo, int K2, int N)
{
    int idx = blockIdx.x * 256 + threadIdx.x;
    if (idx >= K2 * N) return;
    int k2 = idx / N, n = idx - k2 * N;
    float f0 = src[(size_t)(2 * k2) * N + n];
    float f1 = src[(size_t)(2 * k2 + 1) * N + n];
    unsigned h, l;
    bfsplit2(f0, f1, h, l);
    size_t o = widx(k2, n, N);
    hi[o] = h; lo[o] = l;
}
__global__ __launch_bounds__(256) void split_act(
    const float2* __restrict__ src, unsigned* __restrict__ hi,
    unsigned* __restrict__ lo, int total, int K2)
{
    int idx = blockIdx.x * 256 + threadIdx.x;
    if (idx >= total) return;
    float2 f = src[idx];
    unsigned h, l;
    bfsplit2(f.x, f.y, h, l);
    int m = idx / K2, k2 = idx - m * K2;
    size_t o = aidx(m, k2, K2);
    hi[o] = h; lo[o] = l;
}

// ---------------------------------------------------------------------------
// GEMM core: CTA 128x128, 16-k chunks, 3-stage cp.async pipeline, 8 warps
// (2x4), warp tile 64x32. Stage (bytes): Ahi 4K | Alo 4K | Bhi 4K | Blo 4K.
// Frag feeds: A = 1 LDS.128, B = 1 LDS.64.
// ---------------------------------------------------------------------------
#define STG_B 16384
#define G_SMEM (3 * STG_B)

__device__ __forceinline__ void gemm_core(
    const unsigned* __restrict__ Ahi, const unsigned* __restrict__ Alo,
    const unsigned* __restrict__ Whi, const unsigned* __restrict__ Wlo,
    int K2, int N, int kc0, int T, int bm, int bn,
    char* smem, float acc[4][4][4])
{
    const uint32_t sb = smem_u32(smem);
    const int tid = threadIdx.x, lane = tid & 31, warp = tid >> 5;
    const int wr = warp >> 2, wc = warp & 3;
    const int g = lane >> 2, tg = lane & 3;
    const int KC = K2 >> 3;
    const int gi = tid >> 5, li = tid & 31;

    auto issue = [&](int t) {
        const uint32_t st = sb + (uint32_t)(t % 3) * STG_B;
        const int c = kc0 + t;
        const size_t ao = ((size_t)((bm >> 4) + gi) * KC + c) * 128 + li * 4;
        cp16(st + gi * 512 + li * 16, Ahi + ao);
        cp16(st + 4096 + gi * 512 + li * 16, Alo + ao);
        const size_t wo = ((size_t)c * N + bn) * 8 + tid * 4;
        cp16(st + 8192 + tid * 16, Whi + wo);
        cp16(st + 12288 + tid * 16, Wlo + wo);
        asm volatile("cp.async.commit_group;" ::: "memory");
    };
    auto compute = [&](int t) {
        const char* S = smem + (size_t)(t % 3) * STG_B;
        unsigned ah[4][4], al_[4][4];
        #pragma unroll
        for (int i = 0; i < 4; i++) {
            uint4 u = *(const uint4*)(S + (wr * 4 + i) * 512 + lane * 16);
            ah[i][0] = u.x; ah[i][1] = u.y; ah[i][2] = u.z; ah[i][3] = u.w;
            uint4 v = *(const uint4*)(S + 4096 + (wr * 4 + i) * 512 + lane * 16);
            al_[i][0] = v.x; al_[i][1] = v.y; al_[i][2] = v.z; al_[i][3] = v.w;
        }
        #pragma unroll
        for (int j = 0; j < 4; j++) {
            const int nl = wc * 32 + j * 8 + g;
            uint2 bh = *(const uint2*)(S + 8192 + nl * 32 + tg * 8);
            uint2 bl = *(const uint2*)(S + 12288 + nl * 32 + tg * 8);
            unsigned bh2[2] = {bh.x, bh.y};
            unsigned bl2[2] = {bl.x, bl.y};
            #pragma unroll
            for (int i = 0; i < 4; i++) {
                mma16(acc[i][j], ah[i],  bh2);
                mma16(acc[i][j], ah[i],  bl2);
                mma16(acc[i][j], al_[i], bh2);
            }
        }
    };

    issue(0);
    if (T > 1) issue(1);
    for (int t = 0; t < T; t++) {
        asm volatile("cp.async.wait_group 1;" ::: "memory");
        __syncthreads();
        compute(t);
        if (t + 2 < T) issue(t + 2);
        else asm volatile("cp.async.commit_group;" ::: "memory");
        __syncthreads();
    }
}

#define HH2W (Hc * Hc / 2)

// ---- fused 6-way QKV ----
__global__ __launch_bounds__(256, 2) void gemm_qkv6(
    const unsigned* __restrict__ hsh, const unsigned* __restrict__ hsl,
    const unsigned* __restrict__ esh, const unsigned* __restrict__ esl,
    const unsigned* __restrict__ wsah, const unsigned* __restrict__ wsal,
    const unsigned* __restrict__ wcah, const unsigned* __restrict__ wcal,
    const float* __restrict__ bsa, const float* __restrict__ bca,
    float* __restrict__ Oqs, float* __restrict__ Oks, float* __restrict__ Ovs,
    float* __restrict__ Oqc, float* __restrict__ Okc, float* __restrict__ Ovc)
{
    extern __shared__ char smem[];
    const int z = blockIdx.z;
    const int self = (z < 3) ? 1 : 0;
    const int wz = self ? z : (z - 3);
    const unsigned* Ahi = (z <= 3) ? hsh : esh;
    const unsigned* Alo = (z <= 3) ? hsl : esl;
    const unsigned* Whi = (self ? wsah : wcah) + (size_t)wz * HH2W;
    const unsigned* Wlo = (self ? wsal : wcal) + (size_t)wz * HH2W;
    const float* bz = (self ? bsa : bca) + wz * Hc;
    const int bm = blockIdx.y * 128, bn = blockIdx.x * 128;

    float acc[4][4][4];
    #pragma unroll
    for (int i = 0; i < 4; i++)
        #pragma unroll
        for (int j = 0; j < 4; j++)
            #pragma unroll
            for (int r = 0; r < 4; r++) acc[i][j][r] = 0.f;

    gemm_core(Ahi, Alo, Whi, Wlo, Hc / 2, Hc, 0, Hc / 16, bm, bn, smem, acc);

    float* C = (z == 0) ? Oqs : (z == 1) ? Oks : (z == 2) ? Ovs
             : (z == 3) ? Oqc : (z == 4) ? Okc : Ovc;
    const int lane = threadIdx.x & 31, warp = threadIdx.x >> 5;
    const int wr = warp >> 2, wc = warp & 3, g = lane >> 2, tg = lane & 3;
    #pragma unroll
    for (int i = 0; i < 4; i++) {
        int row0 = bm + wr * 64 + i * 16 + g;
        #pragma unroll
        for (int j = 0; j < 4; j++) {
            int col = bn + wc * 32 + j * 8 + 2 * tg;
            float2 b2 = *(const float2*)(bz + col);
            *(float2*)(C + (size_t)row0 * Hc + col) =
                make_float2(acc[i][j][0] + b2.x, acc[i][j][1] + b2.y);
            *(float2*)(C + (size_t)(row0 + 8) * Hc + col) =
                make_float2(acc[i][j][2] + b2.x, acc[i][j][3] + b2.y);
        }
    }
}

// ---- direct GEMM with split epilogue (FFN-up) ----
__global__ __launch_bounds__(256, 2) void gemm_ps(
    const unsigned* __restrict__ Ahi, const unsigned* __restrict__ Alo,
    const unsigned* __restrict__ Whi, const unsigned* __restrict__ Wlo,
    const float* __restrict__ bias,
    unsigned* __restrict__ Chi, unsigned* __restrict__ Clo,
    int N, int K, int fuse_gelu)
{
    extern __shared__ char smem[];
    const int bm = blockIdx.y * 128, bn = blockIdx.x * 128;
    float acc[4][4][4];
    #pragma unroll
    for (int i = 0; i < 4; i++)
        #pragma unroll
        for (int j = 0; j < 4; j++)
            #pragma unroll
            for (int r = 0; r < 4; r++) acc[i][j][r] = 0.f;

    gemm_core(Ahi, Alo, Whi, Wlo, K / 2, N, 0, K / 16, bm, bn, smem, acc);

    const int lane = threadIdx.x & 31, warp = threadIdx.x >> 5;
    const int wr = warp >> 2, wc = warp & 3, g = lane >> 2, tg = lane & 3;
    const int N2 = N >> 1;
    #pragma unroll
    for (int i = 0; i < 4; i++) {
        int row0 = bm + wr * 64 + i * 16 + g;
        #pragma unroll
        for (int j = 0; j < 4; j++) {
            int col = bn + wc * 32 + j * 8 + 2 * tg;
            float2 b2 = *(const float2*)(bias + col);
            float v0 = acc[i][j][0] + b2.x, v1 = acc[i][j][1] + b2.y;
            float v2 = acc[i][j][2] + b2.x, v3 = acc[i][j][3] + b2.y;
            if (fuse_gelu) {
                v0 = gelu_new(v0); v1 = gelu_new(v1);
                v2 = gelu_new(v2); v3 = gelu_new(v3);
            }
            unsigned h0, l0, h1, l1;
            bfsplit2(v0, v1, h0, l0);
            bfsplit2(v2, v3, h1, l1);
            size_t w0 = aidx(row0, col >> 1, N2);
            size_t w1 = aidx(row0 + 8, col >> 1, N2);
            Chi[w0] = h0; Clo[w0] = l0;
            Chi[w1] = h1; Clo[w1] = l1;
        }
    }
}

// ---- split-K GEMM -> fp32 partial slice z ----
__global__ __launch_bounds__(256, 2) void gemm_pk(
    const unsigned* __restrict__ Ahi, const unsigned* __restrict__ Alo,
    const unsigned* __restrict__ Whi, const unsigned* __restrict__ Wlo,
    float* __restrict__ P, int K)
{
    extern __shared__ char smem[];
    const int z = blockIdx.z, Z = gridDim.z;
    const int Tc = K / 16 / Z;
    const int bm = blockIdx.y * 128, bn = blockIdx.x * 128;
    float acc[4][4][4];
    #pragma unroll
    for (int i = 0; i < 4; i++)
        #pragma unroll
        for (int j = 0; j < 4; j++)
            #pragma unroll
            for (int r = 0; r < 4; r++) acc[i][j][r] = 0.f;

    gemm_core(Ahi, Alo, Whi, Wlo, K / 2, Hc, z * Tc, Tc, bm, bn, smem, acc);

    float* Pz = P + (size_t)z * Mrows * Hc;
    const int lane = threadIdx.x & 31, warp = threadIdx.x >> 5;
    const int wr = warp >> 2, wc = warp & 3, g = lane >> 2, tg = lane & 3;
    #pragma unroll
    for (int i = 0; i < 4; i++) {
        int row0 = bm + wr * 64 + i * 16 + g;
        #pragma unroll
        for (int j = 0; j < 4; j++) {
            int col = bn + wc * 32 + j * 8 + 2 * tg;
            *(float2*)(Pz + (size_t)row0 * Hc + col) = make_float2(acc[i][j][0], acc[i][j][1]);
            *(float2*)(Pz + (size_t)(row0 + 8) * Hc + col) = make_float2(acc[i][j][2], acc[i][j][3]);
        }
    }
}

// ---- fused dual out-projection split-K: z01=self, z23=cross ----
__global__ __launch_bounds__(256, 2) void gemm_pk2(
    const unsigned* __restrict__ ash, const unsigned* __restrict__ asl,
    const unsigned* __restrict__ ach, const unsigned* __restrict__ acl,
    const unsigned* __restrict__ wsh, const unsigned* __restrict__ wsl,
    const unsigned* __restrict__ wch, const unsigned* __restrict__ wcl,
    float* __restrict__ P)
{
    extern __shared__ char smem[];
    const int z = blockIdx.z;
    const int sel = z >> 1, zz = z & 1;
    const unsigned* Ahi = sel ? ach : ash;
    const unsigned* Alo = sel ? acl : asl;
    const unsigned* Whi = sel ? wch : wsh;
    const unsigned* Wlo = sel ? wcl : wsl;
    const int bm = blockIdx.y * 128, bn = blockIdx.x * 128;
    float acc[4][4][4];
    #pragma unroll
    for (int i = 0; i < 4; i++)
        #pragma unroll
        for (int j = 0; j < 4; j++)
            #pragma unroll
            for (int r = 0; r < 4; r++) acc[i][j][r] = 0.f;

    gemm_core(Ahi, Alo, Whi, Wlo, Hc / 2, Hc, zz * 32, 32, bm, bn, smem, acc);

    float* Pz = P + (size_t)z * Mrows * Hc;
    const int lane = threadIdx.x & 31, warp = threadIdx.x >> 5;
    const int wr = warp >> 2, wc = warp & 3, g = lane >> 2, tg = lane & 3;
    #pragma unroll
    for (int i = 0; i < 4; i++) {
        int row0 = bm + wr * 64 + i * 16 + g;
        #pragma unroll
        for (int j = 0; j < 4; j++) {
            int col = bn + wc * 32 + j * 8 + 2 * tg;
            *(float2*)(Pz + (size_t)row0 * Hc + col) = make_float2(acc[i][j][0], acc[i][j][1]);
            *(float2*)(Pz + (size_t)(row0 + 8) * Hc + col) = make_float2(acc[i][j][2], acc[i][j][3]);
        }
    }
}

// ---------------------------------------------------------------------------
// Reductions + LayerNorm
// ---------------------------------------------------------------------------
__device__ __forceinline__ float block_sum_256(float v) {
    __shared__ float sh[8];
    #pragma unroll
    for (int o = 16; o > 0; o >>= 1) v += __shfl_xor_sync(0xffffffffu, v, o);
    __syncthreads();
    if ((threadIdx.x & 31) == 0) sh[threadIdx.x >> 5] = v;
    __syncthreads();
    float t = sh[0];
    #pragma unroll
    for (int i = 1; i < 8; i++) t += sh[i];
    return t;
}

__device__ __forceinline__ void ln_body(
    int row, const float* P, int Z, const float* bias, const float* add,
    const float* lnw, float* outF, unsigned* ohi, unsigned* olo)
{
    const int tid = threadIdx.x;
    const size_t MN = (size_t)Mrows * Hc;
    float4 v = ((const float4*)(P + (size_t)row * Hc))[tid];
    for (int z = 1; z < Z; z++) {
        float4 p = ((const float4*)(P + z * MN + (size_t)row * Hc))[tid];
        v.x += p.x; v.y += p.y; v.z += p.z; v.w += p.w;
    }
    float4 b4 = ((const float4*)bias)[tid];
    float4 a4 = ((const float4*)(add + (size_t)row * Hc))[tid];
    v.x += b4.x + a4.x; v.y += b4.y + a4.y; v.z += b4.z + a4.z; v.w += b4.w + a4.w;

    float s = v.x + v.y + v.z + v.w;
    s = block_sum_256(s);
    const float mean = s * (1.f / Hc);
    float dx = v.x - mean, dy = v.y - mean, dz = v.z - mean, dw = v.w - mean;
    float q = dx * dx + dy * dy + dz * dz + dw * dw;
    q = block_sum_256(q);
    const float inv = rsqrtf(q * (1.f / Hc) + LN_EPS);
    float4 gm = ((const float4*)lnw)[tid];
    float4 bt = ((const float4*)(lnw + Hc))[tid];
    float y0 = dx * inv * gm.x + bt.x;
    float y1 = dy * inv * gm.y + bt.y;
    float y2 = dz * inv * gm.z + bt.z;
    float y3 = dw * inv * gm.w + bt.w;
    if (outF)
        ((float4*)(outF + (size_t)row * Hc))[tid] = make_float4(y0, y1, y2, y3);
    if (ohi) {
        unsigned h0, l0, h1, l1;
        bfsplit2(y0, y1, h0, l0);
        bfsplit2(y2, y3, h1, l1);
        size_t o0 = aidx(row, 2 * tid, Hc / 2);
        size_t o1 = aidx(row, 2 * tid + 1, Hc / 2);
        ohi[o0] = h0; olo[o0] = l0;
        ohi[o1] = h1; olo[o1] = l1;
    }
}

__global__ __launch_bounds__(256) void ln_red(
    const float* __restrict__ P, int Z,
    const float* __restrict__ bias, const float* __restrict__ add,
    const float* __restrict__ lnw,
    float* __restrict__ outF, unsigned* __restrict__ ohi, unsigned* __restrict__ olo)
{
    ln_body(blockIdx.x, P, Z, bias, add, lnw, outF, ohi, olo);
}

__global__ __launch_bounds__(256) void ln_red2(
    const float* __restrict__ P,
    const float* __restrict__ bsa, const float* __restrict__ bca,
    const float* __restrict__ add,
    const float* __restrict__ lnsa, const float* __restrict__ lnca,
    unsigned* __restrict__ x1hi, unsigned* __restrict__ x1lo,
    float* __restrict__ x2)
{
    const int row = blockIdx.x & (Mrows - 1);
    const int sel = blockIdx.x >> 11;
    if (sel == 0)
        ln_body(row, P, 2, bsa, add, lnsa, nullptr, x1hi, x1lo);
    else
        ln_body(row, P + 2 * (size_t)Mrows * Hc, 2, bca, add, lnca, x2, nullptr, nullptr);
}

// ---------------------------------------------------------------------------
// Fused self+cross FlashAttention (bf16x2 split, m16n8k16)
// ---------------------------------------------------------------------------
#define LDQ 36
#define LDK 72
#define LDV 72
#define ATTN_SMEM ((2 * 128 * LDQ + 2 * 32 * LDK + 2 * 32 * LDV) * 4 + Sc * 4)

__global__ __launch_bounds__(256) void attn_tc2(
    const float* __restrict__ Qs, const float* __restrict__ Ks_,
    const float* __restrict__ Vs,
    const float* __restrict__ Qc, const float* __restrict__ Kc,
    const float* __restrict__ Vc,
    const int* __restrict__ amask, const int* __restrict__ emask,
    unsigned* __restrict__ ashi, unsigned* __restrict__ aslo,
    unsigned* __restrict__ achi, unsigned* __restrict__ aclo)
{
    extern __shared__ unsigned sm_a[];
    unsigned* Qh = sm_a;
    unsigned* Ql = Qh + 128 * LDQ;
    unsigned* Kh = Ql + 128 * LDQ;
    unsigned* Kl = Kh + 32 * LDK;
    unsigned* Vh = Kl + 32 * LDK;
    unsigned* Vl = Vh + 32 * LDV;
    float* madd = (float*)(Vl + 32 * LDV);

    const int sel = blockIdx.x >> 8;
    const int inner = blockIdx.x & 255;
    const float* Q   = sel ? Qc : Qs;
    const float* Kin = sel ? Kc : Ks_;
    const float* Vin = sel ? Vc : Vs;
    const int* mask  = sel ? emask : amask;
    unsigned* Ohi    = sel ? achi : ashi;
    unsigned* Olo    = sel ? aclo : aslo;

    const int tid = threadIdx.x, lane = tid & 31, warp = tid >> 5;
    const int g = lane >> 2, tg = lane & 3;
    const int qt = inner & 3;
    const int n  = (inner >> 2) & 15;
    const int b  = inner >> 6;

    for (int j = tid; j < Sc; j += 256)
        madd[j] = mask[b * Sc + j] ? 0.f : -10000.f;

    {
        int r = tid >> 1, d0 = (tid & 1) * 32;
        const float* qp = Q + (size_t)(b * Sc + qt * 128 + r) * Hc + n * Dc + d0;
        #pragma unroll
        for (int i = 0; i < 32; i += 8) {
            float4 u = *(const float4*)(qp + i);
            float4 w = *(const float4*)(qp + i + 4);
            unsigned h0, l0, h1, l1, h2, l2, h3, l3;
            bfsplit2(u.x, u.y, h0, l0); bfsplit2(u.z, u.w, h1, l1);
            bfsplit2(w.x, w.y, h2, l2); bfsplit2(w.z, w.w, h3, l3);
            *(uint4*)&Qh[r * LDQ + ((d0 + i) >> 1)] = make_uint4(h0, h1, h2, h3);
            *(uint4*)&Ql[r * LDQ + ((d0 + i) >> 1)] = make_uint4(l0, l1, l2, l3);
        }
    }
    __syncthreads();

    float o[8][4];
    #pragma unroll
    for (int j = 0; j < 8; j++)
        #pragma unroll
        for (int r = 0; r < 4; r++) o[j][r] = 0.f;
    float m_run[2] = {-1e30f, -1e30f};
    float l_run[2] = {0.f, 0.f};

    for (int kv = 0; kv < Sc; kv += 64) {
        {
            int r = tid >> 2, d0 = (tid & 3) * 16;
            const float* kpp = Kin + (size_t)(b * Sc + kv + r) * Hc + n * Dc + d0;
            float4 u = *(const float4*)(kpp);
            float4 w = *(const float4*)(kpp + 4);
            float4 x = *(const float4*)(kpp + 8);
            float4 y = *(const float4*)(kpp + 12);
            float pv[16] = {u.x, u.y, u.z, u.w, w.x, w.y, w.z, w.w,
                            x.x, x.y, x.z, x.w, y.x, y.y, y.z, y.w};
            #pragma unroll
            for (int p = 0; p < 8; p++) {
                unsigned h, l;
                bfsplit2(pv[2 * p], pv[2 * p + 1], h, l);
                Kh[((d0 >> 1) + p) * LDK + r] = h;
                Kl[((d0 >> 1) + p) * LDK + r] = l;
            }
            int kp2 = tid >> 3, dv0 = (tid & 7) * 8;
            const float* v0p = Vin + (size_t)(b * Sc + kv + 2 * kp2) * Hc + n * Dc + dv0;
            float4 a0 = *(const float4*)(v0p);
            float4 a1 = *(const float4*)(v0p + 4);
            float4 b0 = *(const float4*)(v0p + Hc);
            float4 b1 = *(const float4*)(v0p + Hc + 4);
            unsigned hh[8], ll[8];
            bfsplit2(a0.x, b0.x, hh[0], ll[0]); bfsplit2(a0.y, b0.y, hh[1], ll[1]);
            bfsplit2(a0.z, b0.z, hh[2], ll[2]); bfsplit2(a0.w, b0.w, hh[3], ll[3]);
            bfsplit2(a1.x, b1.x, hh[4], ll[4]); bfsplit2(a1.y, b1.y, hh[5], ll[5]);
            bfsplit2(a1.z, b1.z, hh[6], ll[6]); bfsplit2(a1.w, b1.w, hh[7], ll[7]);
            *(uint4*)&Vh[kp2 * LDV + dv0]     = make_uint4(hh[0], hh[1], hh[2], hh[3]);
            *(uint4*)&Vh[kp2 * LDV + dv0 + 4] = make_uint4(hh[4], hh[5], hh[6], hh[7]);
            *(uint4*)&Vl[kp2 * LDV + dv0]     = make_uint4(ll[0], ll[1], ll[2], ll[3]);
            *(uint4*)&Vl[kp2 * LDV + dv0 + 4] = make_uint4(ll[4], ll[5], ll[6], ll[7]);
        }
        __syncthreads();

        float s[8][4];
        #pragma unroll
        for (int j = 0; j < 8; j++)
            #pragma unroll
            for (int r = 0; r < 4; r++) s[j][r] = 0.f;
        #pragma unroll
        for (int kk2 = 0; kk2 < 32; kk2 += 8) {
            int rb = warp * 16 + g;
            unsigned qh[4], ql_[4];
            qh[0] = Qh[rb * LDQ + kk2 + tg];        qh[1] = Qh[(rb + 8) * LDQ + kk2 + tg];
            qh[2] = Qh[rb * LDQ + kk2 + tg + 4];    qh[3] = Qh[(rb + 8) * LDQ + kk2 + tg + 4];
            ql_[0] = Ql[rb * LDQ + kk2 + tg];       ql_[1] = Ql[(rb + 8) * LDQ + kk2 + tg];
            ql_[2] = Ql[rb * LDQ + kk2 + tg + 4];   ql_[3] = Ql[(rb + 8) * LDQ + kk2 + tg + 4];
            #pragma unroll
            for (int j = 0; j < 8; j++) {
                unsigned kh2[2], kl2[2];
                kh2[0] = Kh[(kk2 + tg) * LDK + j * 8 + g];
                kh2[1] = Kh[(kk2 + tg + 4) * LDK + j * 8 + g];
                kl2[0] = Kl[(kk2 + tg) * LDK + j * 8 + g];
                kl2[1] = Kl[(kk2 + tg + 4) * LDK + j * 8 + g];
                mma16(s[j], qh, kh2);
                mma16(s[j], qh, kl2);
                mma16(s[j], ql_, kh2);
            }
        }

        float corr[2];
        #pragma unroll
        for (int r2 = 0; r2 < 2; r2++) {
            float mx = m_run[r2];
            #pragma unroll
            for (int j = 0; j < 8; j++)
                #pragma unroll
                for (int c = 0; c < 2; c++) {
                    float val = s[j][r2 * 2 + c] * 0.125f + madd[kv + j * 8 + 2 * tg + c];
                    s[j][r2 * 2 + c] = val;
                    mx = fmaxf(mx, val);
                }
            mx = fmaxf(mx, __shfl_xor_sync(0xffffffffu, mx, 1));
            mx = fmaxf(mx, __shfl_xor_sync(0xffffffffu, mx, 2));
            corr[r2] = __expf(m_run[r2] - mx);
            m_run[r2] = mx;
            float rs = 0.f;
            #pragma unroll
            for (int j = 0; j < 8; j++)
                #pragma unroll
                for (int c = 0; c < 2; c++) {
                    float e = __expf(s[j][r2 * 2 + c] - mx);
                    s[j][r2 * 2 + c] = e;
                    rs += e;
                }
            rs += __shfl_xor_sync(0xffffffffu, rs, 1);
            rs += __shfl_xor_sync(0xffffffffu, rs, 2);
            l_run[r2] = l_run[r2] * corr[r2] + rs;
        }
        #pragma unroll
        for (int j = 0; j < 8; j++) {
            o[j][0] *= corr[0]; o[j][1] *= corr[0];
            o[j][2] *= corr[1]; o[j][3] *= corr[1];
        }

        #pragma unroll
        for (int kf = 0; kf < 4; kf++) {
            unsigned ph[4], pl[4];
            bfsplit2(s[2 * kf][0],     s[2 * kf][1],     ph[0], pl[0]);
            bfsplit2(s[2 * kf][2],     s[2 * kf][3],     ph[1], pl[1]);
            bfsplit2(s[2 * kf + 1][0], s[2 * kf + 1][1], ph[2], pl[2]);
            bfsplit2(s[2 * kf + 1][2], s[2 * kf + 1][3], ph[3], pl[3]);
            #pragma unroll
            for (int j = 0; j < 8; j++) {
                unsigned vh2[2], vl2[2];
                vh2[0] = Vh[(kf * 8 + tg) * LDV + j * 8 + g];
                vh2[1] = Vh[(kf * 8 + tg + 4) * LDV + j * 8 + g];
                vl2[0] = Vl[(kf * 8 + tg) * LDV + j * 8 + g];
                vl2[1] = Vl[(kf * 8 + tg + 4) * LDV + j * 8 + g];
                mma16(o[j], ph, vh2);
                mma16(o[j], ph, vl2);
                mma16(o[j], pl, vh2);
            }
        }
        __syncthreads();
    }

    float inv0 = 1.f / l_run[0], inv1 = 1.f / l_run[1];
    int row0 = b * Sc + qt * 128 + warp * 16 + g;
    #pragma unroll
    for (int j = 0; j < 8; j++) {
        int wcol = n * 32 + j * 4 + tg;
        unsigned h0, l0, h1, l1;
        bfsplit2(o[j][0] * inv0, o[j][1] * inv0, h0, l0);
        bfsplit2(o[j][2] * inv1, o[j][3] * inv1, h1, l1);
        size_t o0 = aidx(row0, wcol, Hc / 2);
        size_t o1 = aidx(row0 + 8, wcol, Hc / 2);
        Ohi[o0] = h0; Olo[o0] = l0;
        Ohi[o1] = h1; Olo[o1] = l1;
    }
}

// ---------------------------------------------------------------------------
// Orchestration
// ---------------------------------------------------------------------------
extern "C" void kernel_launch(void* const* d_in, const int* in_sizes, int n_in,
                              void* d_out, int out_size)
{
    const float* hidden   = (const float*)d_in[0];
    const float* enc      = (const float*)d_in[1];
    const int*   amask    = (const int*)d_in[2];
    const int*   emask    = (const int*)d_in[3];
    const float* sa_qkv_w = (const float*)d_in[4];
    const float* sa_qkv_b = (const float*)d_in[5];
    const float* sa_out_w = (const float*)d_in[6];
    const float* sa_out_b = (const float*)d_in[7];
    const float* sa_ln    = (const float*)d_in[8];
    const float* ca_qkv_w = (const float*)d_in[9];
    const float* ca_qkv_b = (const float*)d_in[10];
    const float* ca_out_w = (const float*)d_in[11];
    const float* ca_out_b = (const float*)d_in[12];
    const float* ca_ln    = (const float*)d_in[13];
    const float* o1_w     = (const float*)d_in[14];
    const float* o1_b     = (const float*)d_in[15];
    const float* o1_ln    = (const float*)d_in[16];
    const float* ffn_w    = (const float*)d_in[17];
    const float* ffn_b    = (const float*)d_in[18];
    const float* o2_w     = (const float*)d_in[19];
    const float* o2_b     = (const float*)d_in[20];
    const float* o2_ln    = (const float*)d_in[21];
    float* out = (float*)d_out;

    cudaFuncSetAttribute(gemm_qkv6, cudaFuncAttributeMaxDynamicSharedMemorySize, G_SMEM);
    cudaFuncSetAttribute(gemm_ps,   cudaFuncAttributeMaxDynamicSharedMemorySize, G_SMEM);
    cudaFuncSetAttribute(gemm_pk,   cudaFuncAttributeMaxDynamicSharedMemorySize, G_SMEM);
    cudaFuncSetAttribute(gemm_pk2,  cudaFuncAttributeMaxDynamicSharedMemorySize, G_SMEM);
    cudaFuncSetAttribute(attn_tc2,  cudaFuncAttributeMaxDynamicSharedMemorySize, ATTN_SMEM);

    float *h, *q, *k, *v, *qc, *kc, *vc, *x2, *x3, *part;
    unsigned *whi, *wlo;
    unsigned *hs_hi, *hs_lo, *es_hi, *es_lo, *as_hi, *as_lo, *ac_hi, *ac_lo;
    unsigned *x1_hi, *x1_lo, *x3_hi, *x3_lo, *in_hi, *in_lo;
    cudaGetSymbolAddress((void**)&h,  g_h);
    cudaGetSymbolAddress((void**)&q,  g_q);
    cudaGetSymbolAddress((void**)&k,  g_k);
    cudaGetSymbolAddress((void**)&v,  g_v);
    cudaGetSymbolAddress((void**)&qc, g_qc);
    cudaGetSymbolAddress((void**)&kc, g_kc);
    cudaGetSymbolAddress((void**)&vc, g_vc);
    cudaGetSymbolAddress((void**)&x2, g_x2);
    cudaGetSymbolAddress((void**)&x3, g_x3);
    cudaGetSymbolAddress((void**)&part, g_part);
    cudaGetSymbolAddress((void**)&whi, g_whi);
    cudaGetSymbolAddress((void**)&wlo, g_wlo);
    cudaGetSymbolAddress((void**)&hs_hi, g_hs_hi);
    cudaGetSymbolAddress((void**)&hs_lo, g_hs_lo);
    cudaGetSymbolAddress((void**)&es_hi, g_es_hi);
    cudaGetSymbolAddress((void**)&es_lo, g_es_lo);
    cudaGetSymbolAddress((void**)&as_hi, g_as_hi);
    cudaGetSymbolAddress((void**)&as_lo, g_as_lo);
    cudaGetSymbolAddress((void**)&ac_hi, g_ac_hi);
    cudaGetSymbolAddress((void**)&ac_lo, g_ac_lo);
    cudaGetSymbolAddress((void**)&x1_hi, g_x1_hi);
    cudaGetSymbolAddress((void**)&x1_lo, g_x1_lo);
    cudaGetSymbolAddress((void**)&x3_hi, g_x3_hi);
    cudaGetSymbolAddress((void**)&x3_lo, g_x3_lo);
    cudaGetSymbolAddress((void**)&in_hi, g_in_hi);
    cudaGetSymbolAddress((void**)&in_lo, g_in_lo);

    cudaMemcpyAsync(h, hidden, (size_t)Mrows * Hc * sizeof(float),
                    cudaMemcpyDeviceToDevice, 0);

    const size_t FH2W  = (size_t)Hc * Fc / 2;
    const size_t SAQKV = 0;
    const size_t SAOUT = SAQKV + 6 * 3 * (size_t)HH2W;
    const size_t CAQKV = SAOUT + 6 * (size_t)HH2W;
    const size_t CAOUT = CAQKV + 6 * 3 * (size_t)HH2W;
    const size_t O1W   = CAOUT + 6 * (size_t)HH2W;
    const size_t FFW   = O1W   + 6 * (size_t)HH2W;
    const size_t O2W   = FFW   + 6 * FH2W;

    split_w<<<(int)((6 * 3 * (size_t)HH2W + 255) / 256), 256>>>(sa_qkv_w, whi + SAQKV, wlo + SAQKV, 6 * 3 * Hc / 2, Hc);
    split_w<<<(int)((6 * (size_t)HH2W + 255) / 256), 256>>>(sa_out_w, whi + SAOUT, wlo + SAOUT, 6 * Hc / 2, Hc);
    split_w<<<(int)((6 * 3 * (size_t)HH2W + 255) / 256), 256>>>(ca_qkv_w, whi + CAQKV, wlo + CAQKV, 6 * 3 * Hc / 2, Hc);
    split_w<<<(int)((6 * (size_t)HH2W + 255) / 256), 256>>>(ca_out_w, whi + CAOUT, wlo + CAOUT, 6 * Hc / 2, Hc);
    split_w<<<(int)((6 * (size_t)HH2W + 255) / 256), 256>>>(o1_w, whi + O1W, wlo + O1W, 6 * Hc / 2, Hc);
    split_w<<<(int)((6 * FH2W + 255) / 256), 256>>>(ffn_w, whi + FFW, wlo + FFW, 6 * Hc / 2, Fc);
    split_w<<<(int)((6 * FH2W + 255) / 256), 256>>>(o2_w, whi + O2W, wlo + O2W, 6 * Fc / 2, Hc);

    const int ACTW = Mrows * Hc / 2;
    split_act<<<(ACTW + 255) / 256, 256>>>((const float2*)hidden, hs_hi, hs_lo, ACTW, Hc / 2);
    split_act<<<(ACTW + 255) / 256, 256>>>((const float2*)enc, es_hi, es_lo, ACTW, Hc / 2);

    const dim3 gq6(Hc / 128, Mrows / 128, 6);
    const dim3 g2(Hc / 128, Mrows / 128, 2);
    const dim3 g4a(Hc / 128, Mrows / 128, 4);
    const dim3 gF(Fc / 128, Mrows / 128);

    for (int i = 0; i < LAYERS; i++) {
        const size_t saq = SAQKV + (size_t)i * 3 * HH2W;
        const size_t caq = CAQKV + (size_t)i * 3 * HH2W;
        gemm_qkv6<<<gq6, 256, G_SMEM>>>(hs_hi, hs_lo, es_hi, es_lo,
                                        whi + saq, wlo + saq, whi + caq, wlo + caq,
                                        sa_qkv_b + (size_t)i * 3 * Hc,
                                        ca_qkv_b + (size_t)i * 3 * Hc,
                                        q, k, v, qc, kc, vc);
        attn_tc2<<<512, 256, ATTN_SMEM>>>(q, k, v, qc, kc, vc, amask, emask,
                                          as_hi, as_lo, ac_hi, ac_lo);
        gemm_pk2<<<g4a, 256, G_SMEM>>>(as_hi, as_lo, ac_hi, ac_lo,
                                       whi + SAOUT + (size_t)i * HH2W,
                                       wlo + SAOUT + (size_t)i * HH2W,
                                       whi + CAOUT + (size_t)i * HH2W,
                                       wlo + CAOUT + (size_t)i * HH2W, part);
        ln_red2<<<2 * Mrows, 256>>>(part, sa_out_b + (size_t)i * Hc,
                                    ca_out_b + (size_t)i * Hc, h,
                                    sa_ln + (size_t)i * 2 * Hc,
                                    ca_ln + (size_t)i * 2 * Hc,
                                    x1_hi, x1_lo, x2);

        gemm_pk<<<g2, 256, G_SMEM>>>(x1_hi, x1_lo,
                                     whi + O1W + (size_t)i * HH2W,
                                     wlo + O1W + (size_t)i * HH2W, part, Hc);
        ln_red<<<Mrows, 256>>>(part, 2, o1_b + (size_t)i * Hc, x2,
                               o1_ln + (size_t)i * 2 * Hc, x3, x3_hi, x3_lo);

        gemm_ps<<<gF, 256, G_SMEM>>>(x3_hi, x3_lo,
                                     whi + FFW + (size_t)i * FH2W,
                                     wlo + FFW + (size_t)i * FH2W,
                                     ffn_b + (size_t)i * Fc, in_hi, in_lo, Fc, Hc, 1);
        gemm_pk<<<g4a, 256, G_SMEM>>>(in_hi, in_lo,
                                      whi + O2W + (size_t)i * FH2W,
                                      wlo + O2W + (size_t)i * FH2W, part, Fc);
        ln_red<<<Mrows, 256>>>(part, 4, o2_b + (size_t)i * Hc, x3,
                               o2_ln + (size_t)i * 2 * Hc,
                               (i == LAYERS - 1) ? out : h,
                               (i == LAYERS - 1) ? nullptr : hs_hi,
                               (i == LAYERS - 1) ? nullptr : hs_lo);
    }
}